// round 9
// baseline (speedup 1.0000x reference)
#include <cuda_runtime.h>
#include <math.h>

#define NFR 64
#define NPX 65536          // 256*256
#define NTOT (NFR*NPX)     // 4194304 = 2^22
#define M22  0x3FFFFF      // NTOT-1 safety mask
#define SIGMA 0.35355339059327373f
#define TAU   0.35355339059327373f
#define INV1PS (1.0f/(1.0f+SIGMA))
#define ELD 65             // eigen smem leading dim (padded)
#define NSWEEP 8
#define GRAMB 128          // gram partial blocks

#define IDX(i) ((i) & M22)

// ---------------- device globals (scratch) ----------------
__device__ float2 g_D[NTOT];
__device__ float2 g_T[NTOT];
__device__ float2 g_y1[NTOT];
__device__ float2 g_y2[NTOT];
__device__ float2 g_x1[NTOT];
__device__ float2 g_x2[NTOT];
__device__ float2 g_u1[NTOT];
__device__ float2 g_u2[NTOT];
__device__ float2 g_A1[NTOT];
__device__ double g_part[256];
__device__ double g_norm2;
__device__ float2 g_Gp[GRAMB][4096];
__device__ float2 g_Gf[4096];
__device__ float2 g_V[4096];
__device__ float2 g_W[4096];
__device__ float2 g_tw[128];

// ---------------- helpers ----------------
__device__ __forceinline__ float2 cadd(float2 a, float2 b){ return make_float2(a.x+b.x, a.y+b.y); }
__device__ __forceinline__ float2 csub(float2 a, float2 b){ return make_float2(a.x-b.x, a.y-b.y); }
__device__ __forceinline__ float2 cmulf(float2 a, float2 b){ return make_float2(a.x*b.x-a.y*b.y, a.x*b.y+a.y*b.x); }
// conj(s)*a
__device__ __forceinline__ float2 cjmul(float2 s, float2 a){ return make_float2(s.x*a.x+s.y*a.y, s.x*a.y-s.y*a.x); }
__device__ __forceinline__ float2 cscale(float2 a, float c){ return make_float2(a.x*c, a.y*c); }

// 256-pt radix-2 DIT FFT on shared memory, one warp per line.
__device__ __forceinline__ void fft256_sm(float2* s, int stride, int lane, int inv) {
    #pragma unroll
    for (int j = 0; j < 8; j++) {
        int i = lane + (j<<5);
        int r = __brev((unsigned)i) >> 24;
        if (r > i) { float2 a = s[i*stride]; s[i*stride] = s[r*stride]; s[r*stride] = a; }
    }
    __syncwarp();
    #pragma unroll
    for (int st = 0; st < 8; st++) {
        int half = 1 << st;
        #pragma unroll
        for (int j = 0; j < 4; j++) {
            int b  = lane + (j<<5);
            int k  = b & (half-1);
            int i0 = ((b >> st) << (st+1)) + k;
            float2 w = g_tw[(k << (7-st)) & 127];
            if (inv) w.y = -w.y;
            float2 u = s[i0*stride];
            float2 v = s[(i0+half)*stride];
            float2 t = cmulf(w, v);
            s[i0*stride]        = cadd(u, t);
            s[(i0+half)*stride] = csub(u, t);
        }
        __syncwarp();
    }
}

// ---------------- init ----------------
__global__ __launch_bounds__(128) void k_init() {
    int t = threadIdx.x & 127;
    double a = -2.0 * 3.14159265358979323846 * (double)t / 256.0;
    g_tw[t] = make_float2((float)cos(a), (float)sin(a));
}

// block-partial sum of |d|^2, deterministic; reads capped at 'cap' elements
__global__ __launch_bounds__(256) void k_sumsq(const float* __restrict__ dr, const float* __restrict__ di, int cap) {
    double acc = 0.0;
    for (int i = blockIdx.x*blockDim.x + threadIdx.x; i < cap; i += gridDim.x*blockDim.x) {
        float a = dr[i], b = di[i];
        acc += (double)a*(double)a + (double)b*(double)b;
    }
    __shared__ double ws[256];
    ws[threadIdx.x] = acc;
    __syncthreads();
    for (int o = 128; o; o >>= 1) {
        if (threadIdx.x < o) ws[threadIdx.x] += ws[threadIdx.x + o];
        __syncthreads();
    }
    if (threadIdx.x == 0) g_part[blockIdx.x & 255] = ws[0];
}

__global__ __launch_bounds__(256) void k_normred() {
    __shared__ double ws[256];
    ws[threadIdx.x] = g_part[threadIdx.x & 255];
    __syncthreads();
    for (int o = 128; o; o >>= 1) {
        if (threadIdx.x < o) ws[threadIdx.x] += ws[threadIdx.x + o];
        __syncthreads();
    }
    if (threadIdx.x == 0) g_norm2 = ws[0];
}

__global__ __launch_bounds__(256) void k_buildD(const float* __restrict__ dr, const float* __restrict__ di, int cap) {
    float inv = (float)(1.0 / sqrt(g_norm2));
    for (int i = blockIdx.x*blockDim.x + threadIdx.x; i < NTOT; i += gridDim.x*blockDim.x) {
        float a = (i < cap) ? dr[i] : 0.f;
        float b = (i < cap) ? di[i] : 0.f;
        g_D[IDX(i)]  = make_float2(a*inv, b*inv);
        g_y1[IDX(i)] = make_float2(0.f, 0.f);
        g_y2[IDX(i)] = make_float2(0.f, 0.f);
    }
}

// ---------------- FFT row pass ----------------
// mode 0: D (inverse, startpoint). mode 1: u1+u2 (forward) + fused y2 dual update.
// mode 2: y1 (inverse). Output scaled rows -> g_T.
__global__ __launch_bounds__(256) void k_fft_row(int mode, int inv, const float* __restrict__ lamSp, int lamIdx) {
    __shared__ float2 sm[8*256];
    int warp = threadIdx.x >> 5, lane = threadIdx.x & 31;
    int line = (blockIdx.x << 3) + warp;
    int base = line << 8;
    int f = line >> 8;
    float2* s = sm + (warp << 8);
    if (mode == 1) {
        float lamS = lamSp ? fmaxf(lamSp[lamIdx], 0.f) : 0.01f;
        float l2 = lamS*lamS;
        #pragma unroll
        for (int j = 0; j < 8; j++) {
            int i = lane + (j<<5);
            float2 u1v = g_u1[IDX(base+i)];
            float2 u2v = g_u2[IDX(base+i)];
            s[i] = cadd(u1v, u2v);
            // fused y2 update: a = y2 + sigma*(u2[f+1]-u2[f]); project onto lamS-ball
            float2 a = g_y2[IDX(base+i)];
            if (f < NFR-1) {
                float2 un = g_u2[IDX(base+i+NPX)];
                a.x += SIGMA*(un.x - u2v.x);
                a.y += SIGMA*(un.y - u2v.y);
            }
            float m2 = a.x*a.x + a.y*a.y;
            if (m2 > l2) {
                float sc = lamS * rsqrtf(m2);
                a.x *= sc; a.y *= sc;
            }
            g_y2[IDX(base+i)] = a;
        }
    } else if (mode == 0) {
        #pragma unroll
        for (int j = 0; j < 8; j++) { int i = lane + (j<<5); s[i] = g_D[IDX(base+i)]; }
    } else {
        #pragma unroll
        for (int j = 0; j < 8; j++) { int i = lane + (j<<5); s[i] = g_y1[IDX(base+i)]; }
    }
    __syncwarp();
    fft256_sm(s, 1, lane, inv);
    #pragma unroll
    for (int j = 0; j < 8; j++) {
        int i = lane + (j<<5);
        float2 v = s[i];
        g_T[IDX(base+i)] = make_float2(v.x*0.0625f, v.y*0.0625f);
    }
}

// ---------------- column-pass common ----------------
__device__ __forceinline__ void col_load_fft(float2* sm, int fb, int x0, int inv) {
    int lx = threadIdx.x & 7, ly = threadIdx.x >> 3;
    #pragma unroll
    for (int i2 = 0; i2 < 8; i2++) {
        int y = (i2<<5) + ly;
        sm[y*9 + lx] = g_T[IDX(fb + (y<<8) + x0 + lx)];
    }
    __syncthreads();
    int warp = threadIdx.x >> 5, lane = threadIdx.x & 31;
    fft256_sm(sm + warp, 9, lane, inv);
    __syncthreads();
}

// startpoint: broadcast ifft result into x1,x2,u1,u2
__global__ __launch_bounds__(256) void k_col_start() {
    __shared__ float2 sm[256*9];
    int f = blockIdx.x >> 5, x0 = (blockIdx.x & 31) << 3;
    int fb = f << 16;
    col_load_fft(sm, fb, x0, 1);
    int lx = threadIdx.x & 7, ly = threadIdx.x >> 3;
    #pragma unroll
    for (int i2 = 0; i2 < 8; i2++) {
        int y = (i2<<5) + ly;
        int idx = IDX(fb + (y<<8) + x0 + lx);
        float2 v = sm[y*9 + lx];
        v = make_float2(v.x*0.0625f, v.y*0.0625f);
        g_x1[idx] = v; g_x2[idx] = v; g_u1[idx] = v; g_u2[idx] = v;
    }
}

// forward col pass + y1 dual update: y1' = (y1 + sigma*(Ku1 - D))/(1+sigma)
__global__ __launch_bounds__(256) void k_col_y1() {
    __shared__ float2 sm[256*9];
    int f = blockIdx.x >> 5, x0 = (blockIdx.x & 31) << 3;
    int fb = f << 16;
    col_load_fft(sm, fb, x0, 0);
    int lx = threadIdx.x & 7, ly = threadIdx.x >> 3;
    #pragma unroll
    for (int i2 = 0; i2 < 8; i2++) {
        int y = (i2<<5) + ly;
        int idx = IDX(fb + (y<<8) + x0 + lx);
        float2 v = sm[y*9 + lx];
        v = make_float2(v.x*0.0625f, v.y*0.0625f);
        float2 d = g_D[idx];
        float2 yv = g_y1[idx];
        yv.x = (yv.x + SIGMA*(v.x - d.x)) * INV1PS;
        yv.y = (yv.y + SIGMA*(v.y - d.y)) * INV1PS;
        g_y1[idx] = yv;
    }
}

// inverse col pass -> Kadjy1; fused argg1 = x1 - tau*Kadjy1 and x2/u2 updates
__global__ __launch_bounds__(256) void k_col_kadj() {
    __shared__ float2 sm[256*9];
    int f = blockIdx.x >> 5, x0 = (blockIdx.x & 31) << 3;
    int fb = f << 16;
    col_load_fft(sm, fb, x0, 1);
    int lx = threadIdx.x & 7, ly = threadIdx.x >> 3;
    #pragma unroll
    for (int i2 = 0; i2 < 8; i2++) {
        int y = (i2<<5) + ly;
        int idx = IDX(fb + (y<<8) + x0 + lx);
        float2 v = sm[y*9 + lx];
        v = make_float2(v.x*0.0625f, v.y*0.0625f);    // Kadjy1
        float2 x = g_x1[idx];
        g_A1[idx] = make_float2(x.x - TAU*v.x, x.y - TAU*v.y);
        // fused Kadjy2 + x2/u2 update (branch is block-uniform on f)
        float2 kadj;
        if (f == 0) {
            float2 yc = g_y2[idx];
            kadj = make_float2(v.x - yc.x, v.y - yc.y);
        } else if (f == NFR-1) {
            float2 ym = g_y2[IDX(idx - NPX)];
            kadj = make_float2(v.x + ym.x, v.y + ym.y);
        } else {
            float2 yc = g_y2[idx];
            float2 ym = g_y2[IDX(idx - NPX)];
            kadj = make_float2(v.x - (yc.x - ym.x), v.y - (yc.y - ym.y));
        }
        float2 xo = g_x2[idx];
        float2 xn = make_float2(xo.x - TAU*kadj.x, xo.y - TAU*kadj.y);
        g_x2[idx] = xn;
        g_u2[idx] = make_float2(2.f*xn.x - xo.x, 2.f*xn.y - xo.y);
    }
}

// Gram partials: Gp[b][g*64+h] = sum_{p in block b} conj(A1[g][p]) * A1[h][p]
__global__ __launch_bounds__(256) void k_gram() {
    __shared__ float2 tile[64][33];
    int tid = threadIdx.x;
    int g  = tid & 63;
    int h0 = (tid >> 6) << 4;
    float2 acc[16];
    #pragma unroll
    for (int j = 0; j < 16; j++) acc[j] = make_float2(0.f, 0.f);
    int p0 = blockIdx.x * (NPX / GRAMB);   // 512 pixels per block
    for (int pt = 0; pt < NPX/GRAMB; pt += 32) {
        for (int l = tid; l < 2048; l += 256) {
            int gg = l >> 5, pp = l & 31;
            tile[gg][pp] = g_A1[IDX(gg*NPX + p0 + pt + pp)];
        }
        __syncthreads();
        for (int p = 0; p < 32; p++) {
            float2 ag = tile[g][p];
            #pragma unroll
            for (int j = 0; j < 16; j++) {
                float2 b = tile[h0+j][p];
                acc[j].x += ag.x*b.x + ag.y*b.y;   // conj(ag)*b
                acc[j].y += ag.x*b.y - ag.y*b.x;
            }
        }
        __syncthreads();
    }
    #pragma unroll
    for (int j = 0; j < 16; j++) g_Gp[blockIdx.x & (GRAMB-1)][(g*64 + h0 + j) & 4095] = acc[j];
}

// deterministic reduction of gram partials
__global__ __launch_bounds__(256) void k_gramred() {
    int idx = (blockIdx.x*blockDim.x + threadIdx.x) & 4095;
    double sx = 0.0, sy = 0.0;
    for (int b = 0; b < GRAMB; b++) {
        float2 v = g_Gp[b][idx];
        sx += (double)v.x; sy += (double)v.y;
    }
    g_Gf[idx] = make_float2((float)sx, (float)sy);
}

// ---- Single-kernel 64x64 Hermitian eigensolver ----
// Parallel round-robin Jacobi. A in static smem; V in global scratch (g_V).
// Ends with W = V diag(r) V^H where r_i soft-thresholds singular values.
__global__ __launch_bounds__(256) void k_eig(const float* __restrict__ lamLp, int lamIdx) {
    __shared__ float2 A[64*ELD];     // 33,280 B static
    __shared__ int   pr[32], qr[32];
    __shared__ float csr[32];
    __shared__ float2 ssr[32];
    __shared__ float rr[64];
    int tid = threadIdx.x;   // 256 threads

    for (int l = tid; l < 4096; l += 256) {
        int r = l >> 6, c = l & 63;
        A[r*ELD + c] = g_Gf[l & 4095];
        g_V[l & 4095] = (r == c) ? make_float2(1.f, 0.f) : make_float2(0.f, 0.f);
    }
    __syncthreads();

    for (int sweep = 0; sweep < NSWEEP; sweep++) {
        for (int rnd = 0; rnd < 63; rnd++) {
            if (tid < 32) {
                int p, q;
                if (tid == 0) { p = 63; q = rnd; }
                else { p = (rnd + tid) % 63; q = (rnd - tid + 63) % 63; }
                pr[tid] = p; qr[tid] = q;
                float app = A[p*ELD+p].x, aqq = A[q*ELD+q].x;
                float2 apq = A[p*ELD+q];
                float ab = sqrtf(apq.x*apq.x + apq.y*apq.y);
                float c = 1.f; float2 s = make_float2(0.f, 0.f);
                if (ab > 1e-30f) {
                    float tt = (aqq - app) / (2.f*ab);
                    float t  = 1.f / (fabsf(tt) + sqrtf(1.f + tt*tt));
                    if (tt < 0.f) t = -t;
                    c = rsqrtf(1.f + t*t);
                    float sg = t * c;
                    s = make_float2(apq.x/ab*sg, apq.y/ab*sg);
                }
                csr[tid] = c; ssr[tid] = s;
            }
            __syncthreads();
            // merged two-sided update of A: A' = Jr^H (A Jc), 1024 disjoint 2x2 blocks
            for (int t = tid; t < 1024; t += 256) {
                int kr = t >> 5, kc = t & 31;
                int p_r = pr[kr], q_r = qr[kr];
                int p_c = pr[kc], q_c = qr[kc];
                float cc = csr[kc]; float2 sc = ssr[kc];
                float cr = csr[kr]; float2 sr = ssr[kr];
                float2 app = A[p_r*ELD+p_c], apq = A[p_r*ELD+q_c];
                float2 aqp = A[q_r*ELD+p_c], aqq = A[q_r*ELD+q_c];
                // column rotation: b_p = cc*a_p - conj(sc)*a_q ; b_q = sc*a_p + cc*a_q
                float2 bpp = csub(cscale(app, cc), cjmul(sc, apq));
                float2 bpq = cadd(cmulf(sc, app), cscale(apq, cc));
                float2 bqp = csub(cscale(aqp, cc), cjmul(sc, aqq));
                float2 bqq = cadd(cmulf(sc, aqp), cscale(aqq, cc));
                // row rotation: a'_p = cr*b_p - sr*b_q ; a'_q = conj(sr)*b_p + cr*b_q
                A[p_r*ELD+p_c] = csub(cscale(bpp, cr), cmulf(sr, bqp));
                A[p_r*ELD+q_c] = csub(cscale(bpq, cr), cmulf(sr, bqq));
                A[q_r*ELD+p_c] = cadd(cjmul(sr, bpp), cscale(bqp, cr));
                A[q_r*ELD+q_c] = cadd(cjmul(sr, bpq), cscale(bqq, cr));
            }
            // V column update in global scratch (32 KB working set, L1/L2-resident)
            for (int t = tid; t < 2048; t += 256) {
                int k = t >> 6, r = t & 63;
                int p = pr[k], q = qr[k];
                float c = csr[k]; float2 s = ssr[k];
                float2 vp = g_V[(r*64+p) & 4095], vq = g_V[(r*64+q) & 4095];
                g_V[(r*64+p) & 4095] = csub(cscale(vp, c), cjmul(s, vq));
                g_V[(r*64+q) & 4095] = cadd(cmulf(s, vp), cscale(vq, c));
            }
            __syncthreads();
        }
    }

    if (tid == 0) {
        float lmax = 0.f;
        for (int i = 0; i < 64; i++) { float l = A[i*ELD+i].x; if (l > lmax) lmax = l; }
        float lamL = lamLp ? fmaxf(lamLp[lamIdx], 0.f) : 0.8f;
        float thr = sqrtf(fmaxf(lmax, 0.f)) * TAU * lamL;
        for (int i = 0; i < 64; i++) {
            float l  = fmaxf(A[i*ELD+i].x, 0.f);
            float sv = sqrtf(l);
            rr[i] = (sv > thr) ? (sv - thr) / sv : 0.f;
        }
    }
    __syncthreads();
    // W[g][f] = sum_i V[g][i] * r_i * conj(V[f][i])
    int g = tid & 63, f0 = (tid >> 6) << 4;
    for (int j = 0; j < 16; j++) {
        int f = f0 + j;
        float wx = 0.f, wy = 0.f;
        for (int i = 0; i < 64; i++) {
            float2 vg = g_V[(g*64+i) & 4095];
            float2 vf = g_V[(f*64+i) & 4095];
            float r_ = rr[i];
            float ax = vg.x*r_, ay = vg.y*r_;
            wx += ax*vf.x + ay*vf.y;
            wy += ay*vf.x - ax*vf.y;
        }
        g_W[(g*64+f) & 4095] = make_float2(wx, wy);
    }
}

// x1new[f][p] = sum_g A1[g][p] * W[g][f]; u1 = 2*x1new - x1old
__global__ __launch_bounds__(256) void k_gemm() {
    __shared__ float2 Ws[64*64];
    __shared__ float2 Asm[8][64];
    int tid = threadIdx.x;
    for (int l = tid; l < 4096; l += 256) Ws[l] = g_W[l & 4095];
    int px = tid & 63, fq = tid >> 6;
    int p0 = blockIdx.x << 6;
    float2 acc[16];
    #pragma unroll
    for (int j = 0; j < 16; j++) acc[j] = make_float2(0.f, 0.f);
    __syncthreads();
    for (int g0 = 0; g0 < 64; g0 += 8) {
        for (int l = tid; l < 512; l += 256) {
            int gg = l >> 6, pp = l & 63;
            Asm[gg][pp] = g_A1[IDX((g0+gg)*NPX + p0 + pp)];
        }
        __syncthreads();
        #pragma unroll
        for (int gg = 0; gg < 8; gg++) {
            float2 a = Asm[gg][px];
            #pragma unroll
            for (int j = 0; j < 16; j++) {
                float2 w = Ws[((g0+gg)*64 + (fq<<4) + j) & 4095];
                acc[j].x += a.x*w.x - a.y*w.y;
                acc[j].y += a.x*w.y + a.y*w.x;
            }
        }
        __syncthreads();
    }
    #pragma unroll
    for (int j = 0; j < 16; j++) {
        int idx = IDX(((fq<<4)+j)*NPX + p0 + px);
        float2 old = g_x1[idx];
        float2 nv  = acc[j];
        g_x1[idx] = nv;
        g_u1[idx] = make_float2(2.f*nv.x - old.x, 2.f*nv.y - old.y);
    }
}

// Output writer: buffer is out_size float32 elements (evidence: R7 probe clean at
// out_size floats; 2*NTOT-float writes IMA'd). complex64 reference degraded via
// astype(float32) keeps the REAL part -> write re(x1+x2), exactly nf floats.
__global__ __launch_bounds__(256) void k_out(float* __restrict__ out, int nf) {
    for (int i = blockIdx.x*blockDim.x + threadIdx.x; i < nf; i += gridDim.x*blockDim.x) {
        int ii = IDX(i);
        out[i] = g_x1[ii].x + g_x2[ii].x;
    }
}

// ---------------- launch ----------------
extern "C" void kernel_launch(void* const* d_in, const int* in_sizes, int n_in,
                              void* d_out, int out_size) {
    // Identify inputs by reported size; fall back to positional order.
    const float* dr = 0; const float* di = 0;
    const float* lamS = 0; const float* lamL = 0;
    int drCap = 0, diCap = 0, lamScnt = 0, lamLcnt = 0;
    for (int i = 0; i < n_in; i++) {
        int sz = in_sizes[i];
        if (sz >= NTOT) {
            if (!dr)      { dr = (const float*)d_in[i]; drCap = sz; }
            else if (!di) { di = (const float*)d_in[i]; diCap = sz; }
        } else if (sz > 0) {
            if (!lamS)      { lamS = (const float*)d_in[i]; lamScnt = sz; }
            else if (!lamL) { lamL = (const float*)d_in[i]; lamLcnt = sz; }
        }
    }
    if (!dr && n_in > 0) { dr = (const float*)d_in[0]; drCap = in_sizes[0]; }
    if (!di && n_in > 1) { di = (const float*)d_in[1]; diCap = in_sizes[1]; }
    int cap = drCap < diCap ? drCap : diCap;
    if (cap > NTOT) cap = NTOT;
    if (cap < 0) cap = 0;

    // NEVER write more than out_size floats (and never more than NTOT).
    int nf = out_size;
    if (nf > NTOT) nf = NTOT;
    if (nf < 0) nf = 0;

    k_init<<<1, 128>>>();
    k_sumsq<<<256, 256>>>(dr, di, cap);
    k_normred<<<1, 256>>>();
    k_buildD<<<4096, 256>>>(dr, di, cap);

    // startpoint = ifft2(D) -> x1, x2, u1, u2
    k_fft_row<<<2048, 256>>>(0, 1, (const float*)0, 0);
    k_col_start<<<2048, 256>>>();

    for (int it = 0; it < 8; it++) {
        int sIdx = (lamScnt > it) ? it : (lamScnt > 0 ? lamScnt - 1 : 0);
        int lIdx = (lamLcnt > it) ? it : (lamLcnt > 0 ? lamLcnt - 1 : 0);
        // Ku1 = fft2(u1+u2) rows (+ fused y2 dual update), then cols + y1 update
        k_fft_row<<<2048, 256>>>(1, 0, lamS, sIdx);
        k_col_y1<<<2048, 256>>>();
        // Kadjy1 = ifft2(y1); argg1 = x1 - tau*Kadjy1; fused x2/u2 update
        k_fft_row<<<2048, 256>>>(2, 1, (const float*)0, 0);
        k_col_kadj<<<2048, 256>>>();
        // low-rank prox via Gram eigendecomposition
        k_gram<<<GRAMB, 256>>>();
        k_gramred<<<16, 256>>>();
        k_eig<<<1, 256>>>(lamL, lIdx);
        k_gemm<<<1024, 256>>>();
    }

    k_out<<<4096, 256>>>((float*)d_out, nf);
}

// round 10
// speedup vs baseline: 3.9825x; 3.9825x over previous
#include <cuda_runtime.h>
#include <math.h>

#define NFR 64
#define NPX 65536          // 256*256
#define NTOT (NFR*NPX)     // 4194304 = 2^22
#define M22  0x3FFFFF      // NTOT-1 safety mask
#define SIGMA 0.35355339059327373f
#define TAU   0.35355339059327373f
#define INV1PS (1.0f/(1.0f+SIGMA))
#define ELD 65             // eigen smem leading dim (padded)
#define NSWEEP 7
#define GRAMB 128          // gram partial blocks

#define IDX(i) ((i) & M22)

// ---------------- device globals (scratch) ----------------
__device__ float2 g_D[NTOT];
__device__ float2 g_T[NTOT];
__device__ float2 g_y1[NTOT];
__device__ float2 g_y2[NTOT];
__device__ float2 g_x1[NTOT];
__device__ float2 g_x2[NTOT];
__device__ float2 g_u1[NTOT];
__device__ float2 g_u2[NTOT];
__device__ float2 g_A1[NTOT];
__device__ double g_part[256];
__device__ double g_norm2;
__device__ float2 g_Gp[GRAMB][4096];
__device__ float2 g_Gf[4096];
__device__ float2 g_W[4096];
__device__ float2 g_tw[128];

// ---------------- helpers ----------------
__device__ __forceinline__ float2 cadd(float2 a, float2 b){ return make_float2(a.x+b.x, a.y+b.y); }
__device__ __forceinline__ float2 csub(float2 a, float2 b){ return make_float2(a.x-b.x, a.y-b.y); }
__device__ __forceinline__ float2 cmulf(float2 a, float2 b){ return make_float2(a.x*b.x-a.y*b.y, a.x*b.y+a.y*b.x); }
// conj(s)*a
__device__ __forceinline__ float2 cjmul(float2 s, float2 a){ return make_float2(s.x*a.x+s.y*a.y, s.x*a.y-s.y*a.x); }
__device__ __forceinline__ float2 cscale(float2 a, float c){ return make_float2(a.x*c, a.y*c); }

// 256-pt radix-2 DIT FFT on shared memory, one warp per line.
__device__ __forceinline__ void fft256_sm(float2* s, int stride, int lane, int inv) {
    #pragma unroll
    for (int j = 0; j < 8; j++) {
        int i = lane + (j<<5);
        int r = __brev((unsigned)i) >> 24;
        if (r > i) { float2 a = s[i*stride]; s[i*stride] = s[r*stride]; s[r*stride] = a; }
    }
    __syncwarp();
    #pragma unroll
    for (int st = 0; st < 8; st++) {
        int half = 1 << st;
        #pragma unroll
        for (int j = 0; j < 4; j++) {
            int b  = lane + (j<<5);
            int k  = b & (half-1);
            int i0 = ((b >> st) << (st+1)) + k;
            float2 w = g_tw[(k << (7-st)) & 127];
            if (inv) w.y = -w.y;
            float2 u = s[i0*stride];
            float2 v = s[(i0+half)*stride];
            float2 t = cmulf(w, v);
            s[i0*stride]        = cadd(u, t);
            s[(i0+half)*stride] = csub(u, t);
        }
        __syncwarp();
    }
}

// ---------------- init ----------------
__global__ __launch_bounds__(128) void k_init() {
    int t = threadIdx.x & 127;
    double a = -2.0 * 3.14159265358979323846 * (double)t / 256.0;
    g_tw[t] = make_float2((float)cos(a), (float)sin(a));
}

// block-partial sum of |d|^2, deterministic; reads capped at 'cap' elements
__global__ __launch_bounds__(256) void k_sumsq(const float* __restrict__ dr, const float* __restrict__ di, int cap) {
    double acc = 0.0;
    for (int i = blockIdx.x*blockDim.x + threadIdx.x; i < cap; i += gridDim.x*blockDim.x) {
        float a = dr[i], b = di[i];
        acc += (double)a*(double)a + (double)b*(double)b;
    }
    __shared__ double ws[256];
    ws[threadIdx.x] = acc;
    __syncthreads();
    for (int o = 128; o; o >>= 1) {
        if (threadIdx.x < o) ws[threadIdx.x] += ws[threadIdx.x + o];
        __syncthreads();
    }
    if (threadIdx.x == 0) g_part[blockIdx.x & 255] = ws[0];
}

__global__ __launch_bounds__(256) void k_normred() {
    __shared__ double ws[256];
    ws[threadIdx.x] = g_part[threadIdx.x & 255];
    __syncthreads();
    for (int o = 128; o; o >>= 1) {
        if (threadIdx.x < o) ws[threadIdx.x] += ws[threadIdx.x + o];
        __syncthreads();
    }
    if (threadIdx.x == 0) g_norm2 = ws[0];
}

__global__ __launch_bounds__(256) void k_buildD(const float* __restrict__ dr, const float* __restrict__ di, int cap) {
    float inv = (float)(1.0 / sqrt(g_norm2));
    for (int i = blockIdx.x*blockDim.x + threadIdx.x; i < NTOT; i += gridDim.x*blockDim.x) {
        float a = (i < cap) ? dr[i] : 0.f;
        float b = (i < cap) ? di[i] : 0.f;
        g_D[IDX(i)]  = make_float2(a*inv, b*inv);
        g_y1[IDX(i)] = make_float2(0.f, 0.f);
        g_y2[IDX(i)] = make_float2(0.f, 0.f);
    }
}

// ---------------- FFT row pass ----------------
// mode 0: D (inverse, startpoint). mode 1: u1+u2 (forward) + fused y2 dual update.
// mode 2: y1 (inverse). Output scaled rows -> g_T.
__global__ __launch_bounds__(256) void k_fft_row(int mode, int inv, const float* __restrict__ lamSp, int lamIdx) {
    __shared__ float2 sm[8*256];
    int warp = threadIdx.x >> 5, lane = threadIdx.x & 31;
    int line = (blockIdx.x << 3) + warp;
    int base = line << 8;
    int f = line >> 8;
    float2* s = sm + (warp << 8);
    if (mode == 1) {
        float lamS = lamSp ? fmaxf(lamSp[lamIdx], 0.f) : 0.01f;
        float l2 = lamS*lamS;
        #pragma unroll
        for (int j = 0; j < 8; j++) {
            int i = lane + (j<<5);
            float2 u1v = g_u1[IDX(base+i)];
            float2 u2v = g_u2[IDX(base+i)];
            s[i] = cadd(u1v, u2v);
            // fused y2 update: a = y2 + sigma*(u2[f+1]-u2[f]); project onto lamS-ball
            float2 a = g_y2[IDX(base+i)];
            if (f < NFR-1) {
                float2 un = g_u2[IDX(base+i+NPX)];
                a.x += SIGMA*(un.x - u2v.x);
                a.y += SIGMA*(un.y - u2v.y);
            }
            float m2 = a.x*a.x + a.y*a.y;
            if (m2 > l2) {
                float sc = lamS * rsqrtf(m2);
                a.x *= sc; a.y *= sc;
            }
            g_y2[IDX(base+i)] = a;
        }
    } else if (mode == 0) {
        #pragma unroll
        for (int j = 0; j < 8; j++) { int i = lane + (j<<5); s[i] = g_D[IDX(base+i)]; }
    } else {
        #pragma unroll
        for (int j = 0; j < 8; j++) { int i = lane + (j<<5); s[i] = g_y1[IDX(base+i)]; }
    }
    __syncwarp();
    fft256_sm(s, 1, lane, inv);
    #pragma unroll
    for (int j = 0; j < 8; j++) {
        int i = lane + (j<<5);
        float2 v = s[i];
        g_T[IDX(base+i)] = make_float2(v.x*0.0625f, v.y*0.0625f);
    }
}

// ---------------- column-pass common ----------------
__device__ __forceinline__ void col_load_fft(float2* sm, int fb, int x0, int inv) {
    int lx = threadIdx.x & 7, ly = threadIdx.x >> 3;
    #pragma unroll
    for (int i2 = 0; i2 < 8; i2++) {
        int y = (i2<<5) + ly;
        sm[y*9 + lx] = g_T[IDX(fb + (y<<8) + x0 + lx)];
    }
    __syncthreads();
    int warp = threadIdx.x >> 5, lane = threadIdx.x & 31;
    fft256_sm(sm + warp, 9, lane, inv);
    __syncthreads();
}

// startpoint: broadcast ifft result into x1,x2,u1,u2
__global__ __launch_bounds__(256) void k_col_start() {
    __shared__ float2 sm[256*9];
    int f = blockIdx.x >> 5, x0 = (blockIdx.x & 31) << 3;
    int fb = f << 16;
    col_load_fft(sm, fb, x0, 1);
    int lx = threadIdx.x & 7, ly = threadIdx.x >> 3;
    #pragma unroll
    for (int i2 = 0; i2 < 8; i2++) {
        int y = (i2<<5) + ly;
        int idx = IDX(fb + (y<<8) + x0 + lx);
        float2 v = sm[y*9 + lx];
        v = make_float2(v.x*0.0625f, v.y*0.0625f);
        g_x1[idx] = v; g_x2[idx] = v; g_u1[idx] = v; g_u2[idx] = v;
    }
}

// forward col pass + y1 dual update: y1' = (y1 + sigma*(Ku1 - D))/(1+sigma)
__global__ __launch_bounds__(256) void k_col_y1() {
    __shared__ float2 sm[256*9];
    int f = blockIdx.x >> 5, x0 = (blockIdx.x & 31) << 3;
    int fb = f << 16;
    col_load_fft(sm, fb, x0, 0);
    int lx = threadIdx.x & 7, ly = threadIdx.x >> 3;
    #pragma unroll
    for (int i2 = 0; i2 < 8; i2++) {
        int y = (i2<<5) + ly;
        int idx = IDX(fb + (y<<8) + x0 + lx);
        float2 v = sm[y*9 + lx];
        v = make_float2(v.x*0.0625f, v.y*0.0625f);
        float2 d = g_D[idx];
        float2 yv = g_y1[idx];
        yv.x = (yv.x + SIGMA*(v.x - d.x)) * INV1PS;
        yv.y = (yv.y + SIGMA*(v.y - d.y)) * INV1PS;
        g_y1[idx] = yv;
    }
}

// inverse col pass -> Kadjy1; fused argg1 = x1 - tau*Kadjy1 and x2/u2 updates
__global__ __launch_bounds__(256) void k_col_kadj() {
    __shared__ float2 sm[256*9];
    int f = blockIdx.x >> 5, x0 = (blockIdx.x & 31) << 3;
    int fb = f << 16;
    col_load_fft(sm, fb, x0, 1);
    int lx = threadIdx.x & 7, ly = threadIdx.x >> 3;
    #pragma unroll
    for (int i2 = 0; i2 < 8; i2++) {
        int y = (i2<<5) + ly;
        int idx = IDX(fb + (y<<8) + x0 + lx);
        float2 v = sm[y*9 + lx];
        v = make_float2(v.x*0.0625f, v.y*0.0625f);    // Kadjy1
        float2 x = g_x1[idx];
        g_A1[idx] = make_float2(x.x - TAU*v.x, x.y - TAU*v.y);
        // fused Kadjy2 + x2/u2 update (branch is block-uniform on f)
        float2 kadj;
        if (f == 0) {
            float2 yc = g_y2[idx];
            kadj = make_float2(v.x - yc.x, v.y - yc.y);
        } else if (f == NFR-1) {
            float2 ym = g_y2[IDX(idx - NPX)];
            kadj = make_float2(v.x + ym.x, v.y + ym.y);
        } else {
            float2 yc = g_y2[idx];
            float2 ym = g_y2[IDX(idx - NPX)];
            kadj = make_float2(v.x - (yc.x - ym.x), v.y - (yc.y - ym.y));
        }
        float2 xo = g_x2[idx];
        float2 xn = make_float2(xo.x - TAU*kadj.x, xo.y - TAU*kadj.y);
        g_x2[idx] = xn;
        g_u2[idx] = make_float2(2.f*xn.x - xo.x, 2.f*xn.y - xo.y);
    }
}

// Gram partials: Gp[b][g*64+h] = sum_{p in block b} conj(A1[g][p]) * A1[h][p]
__global__ __launch_bounds__(256) void k_gram() {
    __shared__ float2 tile[64][33];
    int tid = threadIdx.x;
    int g  = tid & 63;
    int h0 = (tid >> 6) << 4;
    float2 acc[16];
    #pragma unroll
    for (int j = 0; j < 16; j++) acc[j] = make_float2(0.f, 0.f);
    int p0 = blockIdx.x * (NPX / GRAMB);   // 512 pixels per block
    for (int pt = 0; pt < NPX/GRAMB; pt += 32) {
        for (int l = tid; l < 2048; l += 256) {
            int gg = l >> 5, pp = l & 31;
            tile[gg][pp] = g_A1[IDX(gg*NPX + p0 + pt + pp)];
        }
        __syncthreads();
        for (int p = 0; p < 32; p++) {
            float2 ag = tile[g][p];
            #pragma unroll
            for (int j = 0; j < 16; j++) {
                float2 b = tile[h0+j][p];
                acc[j].x += ag.x*b.x + ag.y*b.y;   // conj(ag)*b
                acc[j].y += ag.x*b.y - ag.y*b.x;
            }
        }
        __syncthreads();
    }
    #pragma unroll
    for (int j = 0; j < 16; j++) g_Gp[blockIdx.x & (GRAMB-1)][(g*64 + h0 + j) & 4095] = acc[j];
}

// deterministic reduction of gram partials
__global__ __launch_bounds__(256) void k_gramred() {
    int idx = (blockIdx.x*blockDim.x + threadIdx.x) & 4095;
    double sx = 0.0, sy = 0.0;
    for (int b = 0; b < GRAMB; b++) {
        float2 v = g_Gp[b][idx];
        sx += (double)v.x; sy += (double)v.y;
    }
    g_Gf[idx] = make_float2((float)sx, (float)sy);
}

// ---- 64x64 Hermitian eigensolver: A and V both in dynamic shared memory ----
// 512 threads; merged two-sided 2x2-block rotation application.
// Ends with W = V diag(r) V^H where r_i soft-thresholds singular values.
__global__ __launch_bounds__(512) void k_eig(const float* __restrict__ lamLp, int lamIdx) {
    extern __shared__ float2 es[];
    float2* A = es;              // 64*ELD
    float2* V = es + 64*ELD;     // 64*ELD
    __shared__ int   pr[32], qr[32];
    __shared__ float csr[32];
    __shared__ float2 ssr[32];
    __shared__ float rr[64];
    int tid = threadIdx.x;   // 512 threads

    for (int l = tid; l < 4096; l += 512) {
        int r = l >> 6, c = l & 63;
        A[r*ELD + c] = g_Gf[l & 4095];
        V[r*ELD + c] = (r == c) ? make_float2(1.f, 0.f) : make_float2(0.f, 0.f);
    }
    __syncthreads();

    for (int sweep = 0; sweep < NSWEEP; sweep++) {
        for (int rnd = 0; rnd < 63; rnd++) {
            if (tid < 32) {
                int p, q;
                if (tid == 0) { p = 63; q = rnd; }
                else { p = (rnd + tid) % 63; q = (rnd - tid + 63) % 63; }
                pr[tid] = p; qr[tid] = q;
                float app = A[p*ELD+p].x, aqq = A[q*ELD+q].x;
                float2 apq = A[p*ELD+q];
                float ab = sqrtf(apq.x*apq.x + apq.y*apq.y);
                float c = 1.f; float2 s = make_float2(0.f, 0.f);
                if (ab > 1e-30f) {
                    float tt = (aqq - app) / (2.f*ab);
                    float t  = 1.f / (fabsf(tt) + sqrtf(1.f + tt*tt));
                    if (tt < 0.f) t = -t;
                    c = rsqrtf(1.f + t*t);
                    float sg = t * c;
                    s = make_float2(apq.x/ab*sg, apq.y/ab*sg);
                }
                csr[tid] = c; ssr[tid] = s;
            }
            __syncthreads();
            // merged two-sided update: A' = Jr^H (A Jc), 1024 disjoint 2x2 blocks
            for (int t = tid; t < 1024; t += 512) {
                int kr = t >> 5, kc = t & 31;
                int p_r = pr[kr], q_r = qr[kr];
                int p_c = pr[kc], q_c = qr[kc];
                float cc = csr[kc]; float2 sc = ssr[kc];
                float cr = csr[kr]; float2 sr = ssr[kr];
                float2 app = A[p_r*ELD+p_c], apq = A[p_r*ELD+q_c];
                float2 aqp = A[q_r*ELD+p_c], aqq = A[q_r*ELD+q_c];
                // column rotation: b_p = cc*a_p - conj(sc)*a_q ; b_q = sc*a_p + cc*a_q
                float2 bpp = csub(cscale(app, cc), cjmul(sc, apq));
                float2 bpq = cadd(cmulf(sc, app), cscale(apq, cc));
                float2 bqp = csub(cscale(aqp, cc), cjmul(sc, aqq));
                float2 bqq = cadd(cmulf(sc, aqp), cscale(aqq, cc));
                // row rotation: a'_p = cr*b_p - sr*b_q ; a'_q = conj(sr)*b_p + cr*b_q
                A[p_r*ELD+p_c] = csub(cscale(bpp, cr), cmulf(sr, bqp));
                A[p_r*ELD+q_c] = csub(cscale(bpq, cr), cmulf(sr, bqq));
                A[q_r*ELD+p_c] = cadd(cjmul(sr, bpp), cscale(bqp, cr));
                A[q_r*ELD+q_c] = cadd(cjmul(sr, bpq), cscale(bqq, cr));
            }
            // V column update (independent of A pass; same barrier window)
            for (int t = tid; t < 2048; t += 512) {
                int k = t >> 6, r = t & 63;
                int p = pr[k], q = qr[k];
                float c = csr[k]; float2 s = ssr[k];
                float2 vp = V[r*ELD+p], vq = V[r*ELD+q];
                V[r*ELD+p] = csub(cscale(vp, c), cjmul(s, vq));
                V[r*ELD+q] = cadd(cmulf(s, vp), cscale(vq, c));
            }
            __syncthreads();
        }
    }

    if (tid == 0) {
        float lmax = 0.f;
        for (int i = 0; i < 64; i++) { float l = A[i*ELD+i].x; if (l > lmax) lmax = l; }
        float lamL = lamLp ? fmaxf(lamLp[lamIdx], 0.f) : 0.8f;
        float thr = sqrtf(fmaxf(lmax, 0.f)) * TAU * lamL;
        for (int i = 0; i < 64; i++) {
            float l  = fmaxf(A[i*ELD+i].x, 0.f);
            float sv = sqrtf(l);
            rr[i] = (sv > thr) ? (sv - thr) / sv : 0.f;
        }
    }
    __syncthreads();
    // W[g][f] = sum_i V[g][i] * r_i * conj(V[f][i])
    int g = tid & 63, f0 = (tid >> 6) << 3;
    for (int j = 0; j < 8; j++) {
        int f = f0 + j;
        float wx = 0.f, wy = 0.f;
        for (int i = 0; i < 64; i++) {
            float2 vg = V[g*ELD+i];
            float2 vf = V[f*ELD+i];
            float r_ = rr[i];
            float ax = vg.x*r_, ay = vg.y*r_;
            wx += ax*vf.x + ay*vf.y;
            wy += ay*vf.x - ax*vf.y;
        }
        g_W[(g*64+f) & 4095] = make_float2(wx, wy);
    }
}

// x1new[f][p] = sum_g A1[g][p] * W[g][f]; u1 = 2*x1new - x1old
__global__ __launch_bounds__(256) void k_gemm() {
    __shared__ float2 Ws[64*64];
    __shared__ float2 Asm[8][64];
    int tid = threadIdx.x;
    for (int l = tid; l < 4096; l += 256) Ws[l] = g_W[l & 4095];
    int px = tid & 63, fq = tid >> 6;
    int p0 = blockIdx.x << 6;
    float2 acc[16];
    #pragma unroll
    for (int j = 0; j < 16; j++) acc[j] = make_float2(0.f, 0.f);
    __syncthreads();
    for (int g0 = 0; g0 < 64; g0 += 8) {
        for (int l = tid; l < 512; l += 256) {
            int gg = l >> 6, pp = l & 63;
            Asm[gg][pp] = g_A1[IDX((g0+gg)*NPX + p0 + pp)];
        }
        __syncthreads();
        #pragma unroll
        for (int gg = 0; gg < 8; gg++) {
            float2 a = Asm[gg][px];
            #pragma unroll
            for (int j = 0; j < 16; j++) {
                float2 w = Ws[((g0+gg)*64 + (fq<<4) + j) & 4095];
                acc[j].x += a.x*w.x - a.y*w.y;
                acc[j].y += a.x*w.y + a.y*w.x;
            }
        }
        __syncthreads();
    }
    #pragma unroll
    for (int j = 0; j < 16; j++) {
        int idx = IDX(((fq<<4)+j)*NPX + p0 + px);
        float2 old = g_x1[idx];
        float2 nv  = acc[j];
        g_x1[idx] = nv;
        g_u1[idx] = make_float2(2.f*nv.x - old.x, 2.f*nv.y - old.y);
    }
}

// Output writer: buffer is out_size float32 elements; write re(x1+x2).
__global__ __launch_bounds__(256) void k_out(float* __restrict__ out, int nf) {
    for (int i = blockIdx.x*blockDim.x + threadIdx.x; i < nf; i += gridDim.x*blockDim.x) {
        int ii = IDX(i);
        out[i] = g_x1[ii].x + g_x2[ii].x;
    }
}

// ---------------- launch ----------------
extern "C" void kernel_launch(void* const* d_in, const int* in_sizes, int n_in,
                              void* d_out, int out_size) {
    // Identify inputs by reported size; fall back to positional order.
    const float* dr = 0; const float* di = 0;
    const float* lamS = 0; const float* lamL = 0;
    int drCap = 0, diCap = 0, lamScnt = 0, lamLcnt = 0;
    for (int i = 0; i < n_in; i++) {
        int sz = in_sizes[i];
        if (sz >= NTOT) {
            if (!dr)      { dr = (const float*)d_in[i]; drCap = sz; }
            else if (!di) { di = (const float*)d_in[i]; diCap = sz; }
        } else if (sz > 0) {
            if (!lamS)      { lamS = (const float*)d_in[i]; lamScnt = sz; }
            else if (!lamL) { lamL = (const float*)d_in[i]; lamLcnt = sz; }
        }
    }
    if (!dr && n_in > 0) { dr = (const float*)d_in[0]; drCap = in_sizes[0]; }
    if (!di && n_in > 1) { di = (const float*)d_in[1]; diCap = in_sizes[1]; }
    int cap = drCap < diCap ? drCap : diCap;
    if (cap > NTOT) cap = NTOT;
    if (cap < 0) cap = 0;

    // NEVER write more than out_size floats (and never more than NTOT).
    int nf = out_size;
    if (nf > NTOT) nf = NTOT;
    if (nf < 0) nf = 0;

    const int eig_smem = (int)(2*64*ELD*sizeof(float2));   // 66,560 B dynamic
    cudaFuncSetAttribute(k_eig, cudaFuncAttributeMaxDynamicSharedMemorySize, eig_smem);

    k_init<<<1, 128>>>();
    k_sumsq<<<256, 256>>>(dr, di, cap);
    k_normred<<<1, 256>>>();
    k_buildD<<<4096, 256>>>(dr, di, cap);

    // startpoint = ifft2(D) -> x1, x2, u1, u2
    k_fft_row<<<2048, 256>>>(0, 1, (const float*)0, 0);
    k_col_start<<<2048, 256>>>();

    for (int it = 0; it < 8; it++) {
        int sIdx = (lamScnt > it) ? it : (lamScnt > 0 ? lamScnt - 1 : 0);
        int lIdx = (lamLcnt > it) ? it : (lamLcnt > 0 ? lamLcnt - 1 : 0);
        // Ku1 = fft2(u1+u2) rows (+ fused y2 dual update), then cols + y1 update
        k_fft_row<<<2048, 256>>>(1, 0, lamS, sIdx);
        k_col_y1<<<2048, 256>>>();
        // Kadjy1 = ifft2(y1); argg1 = x1 - tau*Kadjy1; fused x2/u2 update
        k_fft_row<<<2048, 256>>>(2, 1, (const float*)0, 0);
        k_col_kadj<<<2048, 256>>>();
        // low-rank prox via Gram eigendecomposition (all-smem eigensolver)
        k_gram<<<GRAMB, 256>>>();
        k_gramred<<<16, 256>>>();
        k_eig<<<1, 512, eig_smem>>>(lamL, lIdx);
        k_gemm<<<1024, 256>>>();
    }

    k_out<<<4096, 256>>>((float*)d_out, nf);
}

// round 13
// speedup vs baseline: 4.4458x; 1.1163x over previous
#include <cuda_runtime.h>
#include <math.h>

#define NFR 64
#define NPX 65536          // 256*256
#define NTOT (NFR*NPX)     // 4194304 = 2^22
#define M22  0x3FFFFF      // NTOT-1 safety mask
#define SIGMA 0.35355339059327373f
#define TAU   0.35355339059327373f
#define INV1PS (1.0f/(1.0f+SIGMA))
#define ELD 65             // A smem leading dim (padded)
#define NSWEEP 6
#define GRAMB 128          // gram partial blocks

#define IDX(i) ((i) & M22)

// ---------------- device globals (scratch) ----------------
__device__ float2 g_D[NTOT];
__device__ float2 g_T[NTOT];
__device__ float2 g_y1[NTOT];
__device__ float2 g_y2[NTOT];
__device__ float2 g_x1[NTOT];
__device__ float2 g_x2[NTOT];
__device__ float2 g_u1[NTOT];
__device__ float2 g_u2[NTOT];
__device__ float2 g_A1[NTOT];
__device__ double g_part[256];
__device__ double g_norm2;
__device__ float2 g_Gp[GRAMB][4096];
__device__ float2 g_Gf[4096];
__device__ float2 g_W[4096];
__device__ float2 g_tw[128];

// ---------------- helpers ----------------
__device__ __forceinline__ float2 cadd(float2 a, float2 b){ return make_float2(a.x+b.x, a.y+b.y); }
__device__ __forceinline__ float2 csub(float2 a, float2 b){ return make_float2(a.x-b.x, a.y-b.y); }
__device__ __forceinline__ float2 cmulf(float2 a, float2 b){ return make_float2(a.x*b.x-a.y*b.y, a.x*b.y+a.y*b.x); }
// conj(s)*a
__device__ __forceinline__ float2 cjmul(float2 s, float2 a){ return make_float2(s.x*a.x+s.y*a.y, s.x*a.y-s.y*a.x); }
__device__ __forceinline__ float2 cscale(float2 a, float c){ return make_float2(a.x*c, a.y*c); }

// 256-pt radix-2 DIT FFT on shared memory, one warp per line.
__device__ __forceinline__ void fft256_sm(float2* s, int stride, int lane, int inv) {
    #pragma unroll
    for (int j = 0; j < 8; j++) {
        int i = lane + (j<<5);
        int r = __brev((unsigned)i) >> 24;
        if (r > i) { float2 a = s[i*stride]; s[i*stride] = s[r*stride]; s[r*stride] = a; }
    }
    __syncwarp();
    #pragma unroll
    for (int st = 0; st < 8; st++) {
        int half = 1 << st;
        #pragma unroll
        for (int j = 0; j < 4; j++) {
            int b  = lane + (j<<5);
            int k  = b & (half-1);
            int i0 = ((b >> st) << (st+1)) + k;
            float2 w = g_tw[(k << (7-st)) & 127];
            if (inv) w.y = -w.y;
            float2 u = s[i0*stride];
            float2 v = s[(i0+half)*stride];
            float2 t = cmulf(w, v);
            s[i0*stride]        = cadd(u, t);
            s[(i0+half)*stride] = csub(u, t);
        }
        __syncwarp();
    }
}

// ---------------- init ----------------
__global__ __launch_bounds__(128) void k_init() {
    int t = threadIdx.x & 127;
    double a = -2.0 * 3.14159265358979323846 * (double)t / 256.0;
    g_tw[t] = make_float2((float)cos(a), (float)sin(a));
}

__global__ __launch_bounds__(256) void k_sumsq(const float* __restrict__ dr, const float* __restrict__ di, int cap) {
    double acc = 0.0;
    for (int i = blockIdx.x*blockDim.x + threadIdx.x; i < cap; i += gridDim.x*blockDim.x) {
        float a = dr[i], b = di[i];
        acc += (double)a*(double)a + (double)b*(double)b;
    }
    __shared__ double ws[256];
    ws[threadIdx.x] = acc;
    __syncthreads();
    for (int o = 128; o; o >>= 1) {
        if (threadIdx.x < o) ws[threadIdx.x] += ws[threadIdx.x + o];
        __syncthreads();
    }
    if (threadIdx.x == 0) g_part[blockIdx.x & 255] = ws[0];
}

__global__ __launch_bounds__(256) void k_normred() {
    __shared__ double ws[256];
    ws[threadIdx.x] = g_part[threadIdx.x & 255];
    __syncthreads();
    for (int o = 128; o; o >>= 1) {
        if (threadIdx.x < o) ws[threadIdx.x] += ws[threadIdx.x + o];
        __syncthreads();
    }
    if (threadIdx.x == 0) g_norm2 = ws[0];
}

__global__ __launch_bounds__(256) void k_buildD(const float* __restrict__ dr, const float* __restrict__ di, int cap) {
    float inv = (float)(1.0 / sqrt(g_norm2));
    for (int i = blockIdx.x*blockDim.x + threadIdx.x; i < NTOT; i += gridDim.x*blockDim.x) {
        float a = (i < cap) ? dr[i] : 0.f;
        float b = (i < cap) ? di[i] : 0.f;
        g_D[IDX(i)]  = make_float2(a*inv, b*inv);
        g_y1[IDX(i)] = make_float2(0.f, 0.f);
        g_y2[IDX(i)] = make_float2(0.f, 0.f);
    }
}

// ---------------- FFT row pass ----------------
__global__ __launch_bounds__(256) void k_fft_row(int mode, int inv, const float* __restrict__ lamSp, int lamIdx) {
    __shared__ float2 sm[8*256];
    int warp = threadIdx.x >> 5, lane = threadIdx.x & 31;
    int line = (blockIdx.x << 3) + warp;
    int base = line << 8;
    int f = line >> 8;
    float2* s = sm + (warp << 8);
    if (mode == 1) {
        float lamS = lamSp ? fmaxf(lamSp[lamIdx], 0.f) : 0.01f;
        float l2 = lamS*lamS;
        #pragma unroll
        for (int j = 0; j < 8; j++) {
            int i = lane + (j<<5);
            float2 u1v = g_u1[IDX(base+i)];
            float2 u2v = g_u2[IDX(base+i)];
            s[i] = cadd(u1v, u2v);
            float2 a = g_y2[IDX(base+i)];
            if (f < NFR-1) {
                float2 un = g_u2[IDX(base+i+NPX)];
                a.x += SIGMA*(un.x - u2v.x);
                a.y += SIGMA*(un.y - u2v.y);
            }
            float m2 = a.x*a.x + a.y*a.y;
            if (m2 > l2) {
                float sc = lamS * rsqrtf(m2);
                a.x *= sc; a.y *= sc;
            }
            g_y2[IDX(base+i)] = a;
        }
    } else if (mode == 0) {
        #pragma unroll
        for (int j = 0; j < 8; j++) { int i = lane + (j<<5); s[i] = g_D[IDX(base+i)]; }
    } else {
        #pragma unroll
        for (int j = 0; j < 8; j++) { int i = lane + (j<<5); s[i] = g_y1[IDX(base+i)]; }
    }
    __syncwarp();
    fft256_sm(s, 1, lane, inv);
    #pragma unroll
    for (int j = 0; j < 8; j++) {
        int i = lane + (j<<5);
        float2 v = s[i];
        g_T[IDX(base+i)] = make_float2(v.x*0.0625f, v.y*0.0625f);
    }
}

// ---------------- column-pass common ----------------
__device__ __forceinline__ void col_load_fft(float2* sm, int fb, int x0, int inv) {
    int lx = threadIdx.x & 7, ly = threadIdx.x >> 3;
    #pragma unroll
    for (int i2 = 0; i2 < 8; i2++) {
        int y = (i2<<5) + ly;
        sm[y*9 + lx] = g_T[IDX(fb + (y<<8) + x0 + lx)];
    }
    __syncthreads();
    int warp = threadIdx.x >> 5, lane = threadIdx.x & 31;
    fft256_sm(sm + warp, 9, lane, inv);
    __syncthreads();
}

__global__ __launch_bounds__(256) void k_col_start() {
    __shared__ float2 sm[256*9];
    int f = blockIdx.x >> 5, x0 = (blockIdx.x & 31) << 3;
    int fb = f << 16;
    col_load_fft(sm, fb, x0, 1);
    int lx = threadIdx.x & 7, ly = threadIdx.x >> 3;
    #pragma unroll
    for (int i2 = 0; i2 < 8; i2++) {
        int y = (i2<<5) + ly;
        int idx = IDX(fb + (y<<8) + x0 + lx);
        float2 v = sm[y*9 + lx];
        v = make_float2(v.x*0.0625f, v.y*0.0625f);
        g_x1[idx] = v; g_x2[idx] = v; g_u1[idx] = v; g_u2[idx] = v;
    }
}

__global__ __launch_bounds__(256) void k_col_y1() {
    __shared__ float2 sm[256*9];
    int f = blockIdx.x >> 5, x0 = (blockIdx.x & 31) << 3;
    int fb = f << 16;
    col_load_fft(sm, fb, x0, 0);
    int lx = threadIdx.x & 7, ly = threadIdx.x >> 3;
    #pragma unroll
    for (int i2 = 0; i2 < 8; i2++) {
        int y = (i2<<5) + ly;
        int idx = IDX(fb + (y<<8) + x0 + lx);
        float2 v = sm[y*9 + lx];
        v = make_float2(v.x*0.0625f, v.y*0.0625f);
        float2 d = g_D[idx];
        float2 yv = g_y1[idx];
        yv.x = (yv.x + SIGMA*(v.x - d.x)) * INV1PS;
        yv.y = (yv.y + SIGMA*(v.y - d.y)) * INV1PS;
        g_y1[idx] = yv;
    }
}

__global__ __launch_bounds__(256) void k_col_kadj() {
    __shared__ float2 sm[256*9];
    int f = blockIdx.x >> 5, x0 = (blockIdx.x & 31) << 3;
    int fb = f << 16;
    col_load_fft(sm, fb, x0, 1);
    int lx = threadIdx.x & 7, ly = threadIdx.x >> 3;
    #pragma unroll
    for (int i2 = 0; i2 < 8; i2++) {
        int y = (i2<<5) + ly;
        int idx = IDX(fb + (y<<8) + x0 + lx);
        float2 v = sm[y*9 + lx];
        v = make_float2(v.x*0.0625f, v.y*0.0625f);    // Kadjy1
        float2 x = g_x1[idx];
        g_A1[idx] = make_float2(x.x - TAU*v.x, x.y - TAU*v.y);
        float2 kadj;
        if (f == 0) {
            float2 yc = g_y2[idx];
            kadj = make_float2(v.x - yc.x, v.y - yc.y);
        } else if (f == NFR-1) {
            float2 ym = g_y2[IDX(idx - NPX)];
            kadj = make_float2(v.x + ym.x, v.y + ym.y);
        } else {
            float2 yc = g_y2[idx];
            float2 ym = g_y2[IDX(idx - NPX)];
            kadj = make_float2(v.x - (yc.x - ym.x), v.y - (yc.y - ym.y));
        }
        float2 xo = g_x2[idx];
        float2 xn = make_float2(xo.x - TAU*kadj.x, xo.y - TAU*kadj.y);
        g_x2[idx] = xn;
        g_u2[idx] = make_float2(2.f*xn.x - xo.x, 2.f*xn.y - xo.y);
    }
}

// Gram partials with 4x4 register blocking.
// Thread (ty,tx) computes G[g][h] for g = ty+16i, h = tx+16j (i,j in 0..3).
__global__ __launch_bounds__(256) void k_gram() {
    __shared__ float2 tile[64][33];
    int tid = threadIdx.x;
    int tx = tid & 15, ty = tid >> 4;
    float2 acc[4][4];
    #pragma unroll
    for (int i = 0; i < 4; i++)
        #pragma unroll
        for (int j = 0; j < 4; j++) acc[i][j] = make_float2(0.f, 0.f);
    int p0 = blockIdx.x * (NPX / GRAMB);   // 512 pixels per block
    for (int pt = 0; pt < NPX/GRAMB; pt += 32) {
        for (int l = tid; l < 2048; l += 256) {
            int gg = l >> 5, pp = l & 31;
            tile[gg][pp] = g_A1[IDX(gg*NPX + p0 + pt + pp)];
        }
        __syncthreads();
        for (int p = 0; p < 32; p++) {
            float2 ag[4], bh[4];
            #pragma unroll
            for (int i = 0; i < 4; i++) ag[i] = tile[ty + 16*i][p];
            #pragma unroll
            for (int j = 0; j < 4; j++) bh[j] = tile[tx + 16*j][p];
            #pragma unroll
            for (int i = 0; i < 4; i++)
                #pragma unroll
                for (int j = 0; j < 4; j++) {
                    float2 a = ag[i], b = bh[j];
                    acc[i][j].x += a.x*b.x + a.y*b.y;   // conj(a)*b
                    acc[i][j].y += a.x*b.y - a.y*b.x;
                }
        }
        __syncthreads();
    }
    #pragma unroll
    for (int i = 0; i < 4; i++)
        #pragma unroll
        for (int j = 0; j < 4; j++)
            g_Gp[blockIdx.x & (GRAMB-1)][((ty+16*i)*64 + tx+16*j) & 4095] = acc[i][j];
}

__global__ __launch_bounds__(256) void k_gramred() {
    int idx = (blockIdx.x*blockDim.x + threadIdx.x) & 4095;
    double sx = 0.0, sy = 0.0;
    for (int b = 0; b < GRAMB; b++) {
        float2 v = g_Gp[b][idx];
        sx += (double)v.x; sy += (double)v.y;
    }
    g_Gf[idx] = make_float2((float)sx, (float)sy);
}

// ---- 64x64 Hermitian eigensolver: 1024 threads, A + V^T in dynamic smem ----
// A update: one disjoint 2x2 block per thread. V stored transposed (Vt[i][r])
// so each warp owns pair k and lanes do coalesced float4 updates of rows.
// Ends with W = V diag(r) V^H (soft-thresholded singular values).
__global__ __launch_bounds__(1024) void k_eig(const float* __restrict__ lamLp, int lamIdx) {
    extern __shared__ float2 es[];
    float2* A  = es;             // 64*ELD
    float2* Vt = es + 64*ELD;    // 64*64: Vt[i*64 + r] = V[r][i]
    __shared__ int   pr[32], qr[32];
    __shared__ float csr[32];
    __shared__ float2 ssr[32];
    __shared__ float rr[64];
    int tid = threadIdx.x;   // 1024 threads

    for (int l = tid; l < 4096; l += 1024) {
        int r = l >> 6, c = l & 63;
        A[r*ELD + c] = g_Gf[l & 4095];
        Vt[l & 4095] = (r == c) ? make_float2(1.f, 0.f) : make_float2(0.f, 0.f);
    }
    __syncthreads();

    for (int sweep = 0; sweep < NSWEEP; sweep++) {
        for (int rnd = 0; rnd < 63; rnd++) {
            if (tid < 32) {
                int p, q;
                if (tid == 0) { p = 63; q = rnd; }
                else { p = (rnd + tid) % 63; q = (rnd - tid + 63) % 63; }
                pr[tid] = p; qr[tid] = q;
                float app = A[p*ELD+p].x, aqq = A[q*ELD+q].x;
                float2 apq = A[p*ELD+q];
                float ab = sqrtf(apq.x*apq.x + apq.y*apq.y);
                float c = 1.f; float2 s = make_float2(0.f, 0.f);
                if (ab > 1e-30f) {
                    float tt = (aqq - app) / (2.f*ab);
                    float t  = 1.f / (fabsf(tt) + sqrtf(1.f + tt*tt));
                    if (tt < 0.f) t = -t;
                    c = rsqrtf(1.f + t*t);
                    float sg = t * c;
                    s = make_float2(apq.x/ab*sg, apq.y/ab*sg);
                }
                csr[tid] = c; ssr[tid] = s;
            }
            __syncthreads();
            // A update: A' = Jr^H (A Jc), one disjoint 2x2 block per thread
            {
                int kr = tid >> 5, kc = tid & 31;
                int p_r = pr[kr], q_r = qr[kr];
                int p_c = pr[kc], q_c = qr[kc];
                float cc = csr[kc]; float2 sc = ssr[kc];
                float cr = csr[kr]; float2 sr = ssr[kr];
                float2 app = A[p_r*ELD+p_c], apq = A[p_r*ELD+q_c];
                float2 aqp = A[q_r*ELD+p_c], aqq = A[q_r*ELD+q_c];
                float2 bpp = csub(cscale(app, cc), cjmul(sc, apq));
                float2 bpq = cadd(cmulf(sc, app), cscale(apq, cc));
                float2 bqp = csub(cscale(aqp, cc), cjmul(sc, aqq));
                float2 bqq = cadd(cmulf(sc, aqp), cscale(aqq, cc));
                A[p_r*ELD+p_c] = csub(cscale(bpp, cr), cmulf(sr, bqp));
                A[p_r*ELD+q_c] = csub(cscale(bpq, cr), cmulf(sr, bqq));
                A[q_r*ELD+p_c] = cadd(cjmul(sr, bpp), cscale(bqp, cr));
                A[q_r*ELD+q_c] = cadd(cjmul(sr, bpq), cscale(bqq, cr));
            }
            // V update: warp k handles pair k; lane handles rows r2, r2+1 (float4)
            {
                int k  = tid >> 5;
                int r2 = (tid & 31) << 1;
                int p = pr[k], q = qr[k];
                float c = csr[k]; float2 s = ssr[k];
                float4* vp4 = reinterpret_cast<float4*>(&Vt[p*64 + r2]);
                float4* vq4 = reinterpret_cast<float4*>(&Vt[q*64 + r2]);
                float4 vp = *vp4, vq = *vq4;
                float2 vp0 = make_float2(vp.x, vp.y), vp1 = make_float2(vp.z, vp.w);
                float2 vq0 = make_float2(vq.x, vq.y), vq1 = make_float2(vq.z, vq.w);
                float2 np0 = csub(cscale(vp0, c), cjmul(s, vq0));
                float2 nq0 = cadd(cmulf(s, vp0), cscale(vq0, c));
                float2 np1 = csub(cscale(vp1, c), cjmul(s, vq1));
                float2 nq1 = cadd(cmulf(s, vp1), cscale(vq1, c));
                *vp4 = make_float4(np0.x, np0.y, np1.x, np1.y);
                *vq4 = make_float4(nq0.x, nq0.y, nq1.x, nq1.y);
            }
            __syncthreads();
        }
    }

    if (tid == 0) {
        float lmax = 0.f;
        for (int i = 0; i < 64; i++) { float l = A[i*ELD+i].x; if (l > lmax) lmax = l; }
        float lamL = lamLp ? fmaxf(lamLp[lamIdx], 0.f) : 0.8f;
        float thr = sqrtf(fmaxf(lmax, 0.f)) * TAU * lamL;
        for (int i = 0; i < 64; i++) {
            float l  = fmaxf(A[i*ELD+i].x, 0.f);
            float sv = sqrtf(l);
            rr[i] = (sv > thr) ? (sv - thr) / sv : 0.f;
        }
    }
    __syncthreads();
    // W[g][f] = sum_i Vt[i][g] * r_i * conj(Vt[i][f])
    {
        int g = tid & 63, f0 = (tid >> 6) << 2;
        float2 w[4];
        #pragma unroll
        for (int j = 0; j < 4; j++) w[j] = make_float2(0.f, 0.f);
        for (int i = 0; i < 64; i++) {
            float2 vg = Vt[i*64 + g];
            float r_ = rr[i];
            float ax = vg.x*r_, ay = vg.y*r_;
            #pragma unroll
            for (int j = 0; j < 4; j++) {
                float2 vf = Vt[i*64 + f0 + j];
                w[j].x += ax*vf.x + ay*vf.y;
                w[j].y += ay*vf.x - ax*vf.y;
            }
        }
        #pragma unroll
        for (int j = 0; j < 4; j++)
            g_W[(g*64 + f0 + j) & 4095] = w[j];
    }
}

// x1new[f][p] = sum_g A1[g][p] * W[g][f]; u1 = 2*x1new - x1old
// 4px x 4f register blocking, float4 smem loads.
__global__ __launch_bounds__(256) void k_gemm() {
    __shared__ float2 Ws[64*64];
    __shared__ float2 Asm[8][64];
    int tid = threadIdx.x;
    for (int l = tid; l < 4096; l += 256) Ws[l] = g_W[l & 4095];
    int px0 = (tid & 15) << 2;     // 4 consecutive pixels
    int f0  = (tid >> 4) << 2;     // 4 consecutive frames
    int p0 = blockIdx.x << 6;
    float2 acc[4][4];
    #pragma unroll
    for (int i = 0; i < 4; i++)
        #pragma unroll
        for (int j = 0; j < 4; j++) acc[i][j] = make_float2(0.f, 0.f);
    __syncthreads();
    for (int g0 = 0; g0 < 64; g0 += 8) {
        for (int l = tid; l < 512; l += 256) {
            int gg = l >> 6, pp = l & 63;
            Asm[gg][pp] = g_A1[IDX((g0+gg)*NPX + p0 + pp)];
        }
        __syncthreads();
        #pragma unroll
        for (int gg = 0; gg < 8; gg++) {
            float4 a01 = *reinterpret_cast<const float4*>(&Asm[gg][px0]);
            float4 a23 = *reinterpret_cast<const float4*>(&Asm[gg][px0+2]);
            float4 w01 = *reinterpret_cast<const float4*>(&Ws[(g0+gg)*64 + f0]);
            float4 w23 = *reinterpret_cast<const float4*>(&Ws[(g0+gg)*64 + f0 + 2]);
            float2 a[4] = { make_float2(a01.x,a01.y), make_float2(a01.z,a01.w),
                            make_float2(a23.x,a23.y), make_float2(a23.z,a23.w) };
            float2 w[4] = { make_float2(w01.x,w01.y), make_float2(w01.z,w01.w),
                            make_float2(w23.x,w23.y), make_float2(w23.z,w23.w) };
            #pragma unroll
            for (int i = 0; i < 4; i++)
                #pragma unroll
                for (int j = 0; j < 4; j++) {
                    acc[i][j].x += a[i].x*w[j].x - a[i].y*w[j].y;
                    acc[i][j].y += a[i].x*w[j].y + a[i].y*w[j].x;
                }
        }
        __syncthreads();
    }
    #pragma unroll
    for (int j = 0; j < 4; j++) {
        #pragma unroll
        for (int i = 0; i < 4; i++) {
            int idx = IDX((f0+j)*NPX + p0 + px0 + i);
            float2 old = g_x1[idx];
            float2 nv  = acc[i][j];
            g_x1[idx] = nv;
            g_u1[idx] = make_float2(2.f*nv.x - old.x, 2.f*nv.y - old.y);
        }
    }
}

// Output writer: buffer is out_size float32 elements; write re(x1+x2).
__global__ __launch_bounds__(256) void k_out(float* __restrict__ out, int nf) {
    for (int i = blockIdx.x*blockDim.x + threadIdx.x; i < nf; i += gridDim.x*blockDim.x) {
        int ii = IDX(i);
        out[i] = g_x1[ii].x + g_x2[ii].x;
    }
}

// ---------------- launch ----------------
extern "C" void kernel_launch(void* const* d_in, const int* in_sizes, int n_in,
                              void* d_out, int out_size) {
    const float* dr = 0; const float* di = 0;
    const float* lamS = 0; const float* lamL = 0;
    int drCap = 0, diCap = 0, lamScnt = 0, lamLcnt = 0;
    for (int i = 0; i < n_in; i++) {
        int sz = in_sizes[i];
        if (sz >= NTOT) {
            if (!dr)      { dr = (const float*)d_in[i]; drCap = sz; }
            else if (!di) { di = (const float*)d_in[i]; diCap = sz; }
        } else if (sz > 0) {
            if (!lamS)      { lamS = (const float*)d_in[i]; lamScnt = sz; }
            else if (!lamL) { lamL = (const float*)d_in[i]; lamLcnt = sz; }
        }
    }
    if (!dr && n_in > 0) { dr = (const float*)d_in[0]; drCap = in_sizes[0]; }
    if (!di && n_in > 1) { di = (const float*)d_in[1]; diCap = in_sizes[1]; }
    int cap = drCap < diCap ? drCap : diCap;
    if (cap > NTOT) cap = NTOT;
    if (cap < 0) cap = 0;

    int nf = out_size;
    if (nf > NTOT) nf = NTOT;
    if (nf < 0) nf = 0;

    const int eig_smem = (int)((64*ELD + 64*64) * sizeof(float2));   // 66,048 B
    cudaFuncSetAttribute(k_eig, cudaFuncAttributeMaxDynamicSharedMemorySize, eig_smem);

    k_init<<<1, 128>>>();
    k_sumsq<<<256, 256>>>(dr, di, cap);
    k_normred<<<1, 256>>>();
    k_buildD<<<4096, 256>>>(dr, di, cap);

    // startpoint = ifft2(D) -> x1, x2, u1, u2
    k_fft_row<<<2048, 256>>>(0, 1, (const float*)0, 0);
    k_col_start<<<2048, 256>>>();

    for (int it = 0; it < 8; it++) {
        int sIdx = (lamScnt > it) ? it : (lamScnt > 0 ? lamScnt - 1 : 0);
        int lIdx = (lamLcnt > it) ? it : (lamLcnt > 0 ? lamLcnt - 1 : 0);
        k_fft_row<<<2048, 256>>>(1, 0, lamS, sIdx);
        k_col_y1<<<2048, 256>>>();
        k_fft_row<<<2048, 256>>>(2, 1, (const float*)0, 0);
        k_col_kadj<<<2048, 256>>>();
        k_gram<<<GRAMB, 256>>>();
        k_gramred<<<16, 256>>>();
        k_eig<<<1, 1024, eig_smem>>>(lamL, lIdx);
        k_gemm<<<1024, 256>>>();
    }

    k_out<<<4096, 256>>>((float*)d_out, nf);
}

// round 14
// speedup vs baseline: 4.7902x; 1.0774x over previous
#include <cuda_runtime.h>
#include <math.h>

#define NFR 64
#define NPX 65536          // 256*256
#define NTOT (NFR*NPX)     // 4194304 = 2^22
#define M22  0x3FFFFF      // NTOT-1 safety mask
#define SIGMA 0.35355339059327373f
#define TAU   0.35355339059327373f
#define INV1PS (1.0f/(1.0f+SIGMA))
#define ELD 65             // A smem leading dim (padded)
#define NSWEEP 5
#define GRAMB 128          // gram partial blocks

#define IDX(i) ((i) & M22)

// ---------------- device globals (scratch) ----------------
__device__ float2 g_D[NTOT];
__device__ float2 g_T[NTOT];
__device__ float2 g_y1[NTOT];
__device__ float2 g_y2[NTOT];
__device__ float2 g_x1[NTOT];
__device__ float2 g_x2[NTOT];
__device__ float2 g_u1[NTOT];
__device__ float2 g_u2[NTOT];
__device__ float2 g_A1[NTOT];
__device__ double g_part[256];
__device__ double g_norm2;
__device__ float2 g_Gp[GRAMB][4096];
__device__ float2 g_Gf[4096];
__device__ float2 g_W[4096];
__device__ float2 g_tw[128];

// ---------------- helpers ----------------
__device__ __forceinline__ float2 cadd(float2 a, float2 b){ return make_float2(a.x+b.x, a.y+b.y); }
__device__ __forceinline__ float2 csub(float2 a, float2 b){ return make_float2(a.x-b.x, a.y-b.y); }
__device__ __forceinline__ float2 cmulf(float2 a, float2 b){ return make_float2(a.x*b.x-a.y*b.y, a.x*b.y+a.y*b.x); }
// conj(s)*a
__device__ __forceinline__ float2 cjmul(float2 s, float2 a){ return make_float2(s.x*a.x+s.y*a.y, s.x*a.y-s.y*a.x); }
__device__ __forceinline__ float2 cscale(float2 a, float c){ return make_float2(a.x*c, a.y*c); }

// 256-pt radix-2 DIT FFT on shared memory, one warp per line.
__device__ __forceinline__ void fft256_sm(float2* s, int stride, int lane, int inv) {
    #pragma unroll
    for (int j = 0; j < 8; j++) {
        int i = lane + (j<<5);
        int r = __brev((unsigned)i) >> 24;
        if (r > i) { float2 a = s[i*stride]; s[i*stride] = s[r*stride]; s[r*stride] = a; }
    }
    __syncwarp();
    #pragma unroll
    for (int st = 0; st < 8; st++) {
        int half = 1 << st;
        #pragma unroll
        for (int j = 0; j < 4; j++) {
            int b  = lane + (j<<5);
            int k  = b & (half-1);
            int i0 = ((b >> st) << (st+1)) + k;
            float2 w = g_tw[(k << (7-st)) & 127];
            if (inv) w.y = -w.y;
            float2 u = s[i0*stride];
            float2 v = s[(i0+half)*stride];
            float2 t = cmulf(w, v);
            s[i0*stride]        = cadd(u, t);
            s[(i0+half)*stride] = csub(u, t);
        }
        __syncwarp();
    }
}

// ---------------- init ----------------
__global__ __launch_bounds__(128) void k_init() {
    int t = threadIdx.x & 127;
    double a = -2.0 * 3.14159265358979323846 * (double)t / 256.0;
    g_tw[t] = make_float2((float)cos(a), (float)sin(a));
}

__global__ __launch_bounds__(256) void k_sumsq(const float* __restrict__ dr, const float* __restrict__ di, int cap) {
    double acc = 0.0;
    for (int i = blockIdx.x*blockDim.x + threadIdx.x; i < cap; i += gridDim.x*blockDim.x) {
        float a = dr[i], b = di[i];
        acc += (double)a*(double)a + (double)b*(double)b;
    }
    __shared__ double ws[256];
    ws[threadIdx.x] = acc;
    __syncthreads();
    for (int o = 128; o; o >>= 1) {
        if (threadIdx.x < o) ws[threadIdx.x] += ws[threadIdx.x + o];
        __syncthreads();
    }
    if (threadIdx.x == 0) g_part[blockIdx.x & 255] = ws[0];
}

__global__ __launch_bounds__(256) void k_normred() {
    __shared__ double ws[256];
    ws[threadIdx.x] = g_part[threadIdx.x & 255];
    __syncthreads();
    for (int o = 128; o; o >>= 1) {
        if (threadIdx.x < o) ws[threadIdx.x] += ws[threadIdx.x + o];
        __syncthreads();
    }
    if (threadIdx.x == 0) g_norm2 = ws[0];
}

__global__ __launch_bounds__(256) void k_buildD(const float* __restrict__ dr, const float* __restrict__ di, int cap) {
    float inv = (float)(1.0 / sqrt(g_norm2));
    for (int i = blockIdx.x*blockDim.x + threadIdx.x; i < NTOT; i += gridDim.x*blockDim.x) {
        float a = (i < cap) ? dr[i] : 0.f;
        float b = (i < cap) ? di[i] : 0.f;
        g_D[IDX(i)]  = make_float2(a*inv, b*inv);
        g_y1[IDX(i)] = make_float2(0.f, 0.f);
        g_y2[IDX(i)] = make_float2(0.f, 0.f);
    }
}

// ---------------- FFT row pass ----------------
// mode 0: D (inverse, startpoint). mode 1: u1+u2 (forward) + fused y2 dual update.
__global__ __launch_bounds__(256) void k_fft_row(int mode, int inv, const float* __restrict__ lamSp, int lamIdx) {
    __shared__ float2 sm[8*256];
    int warp = threadIdx.x >> 5, lane = threadIdx.x & 31;
    int line = (blockIdx.x << 3) + warp;
    int base = line << 8;
    int f = line >> 8;
    float2* s = sm + (warp << 8);
    if (mode == 1) {
        float lamS = lamSp ? fmaxf(lamSp[lamIdx], 0.f) : 0.01f;
        float l2 = lamS*lamS;
        #pragma unroll
        for (int j = 0; j < 8; j++) {
            int i = lane + (j<<5);
            float2 u1v = g_u1[IDX(base+i)];
            float2 u2v = g_u2[IDX(base+i)];
            s[i] = cadd(u1v, u2v);
            float2 a = g_y2[IDX(base+i)];
            if (f < NFR-1) {
                float2 un = g_u2[IDX(base+i+NPX)];
                a.x += SIGMA*(un.x - u2v.x);
                a.y += SIGMA*(un.y - u2v.y);
            }
            float m2 = a.x*a.x + a.y*a.y;
            if (m2 > l2) {
                float sc = lamS * rsqrtf(m2);
                a.x *= sc; a.y *= sc;
            }
            g_y2[IDX(base+i)] = a;
        }
    } else {
        #pragma unroll
        for (int j = 0; j < 8; j++) { int i = lane + (j<<5); s[i] = g_D[IDX(base+i)]; }
    }
    __syncwarp();
    fft256_sm(s, 1, lane, inv);
    #pragma unroll
    for (int j = 0; j < 8; j++) {
        int i = lane + (j<<5);
        float2 v = s[i];
        g_T[IDX(base+i)] = make_float2(v.x*0.0625f, v.y*0.0625f);
    }
}

// startpoint: inverse col pass; broadcast result into x1,x2,u1,u2
__global__ __launch_bounds__(256) void k_col_start() {
    __shared__ float2 sm[256*9];
    int f = blockIdx.x >> 5, x0 = (blockIdx.x & 31) << 3;
    int fb = f << 16;
    int lx = threadIdx.x & 7, ly = threadIdx.x >> 3;
    #pragma unroll
    for (int i2 = 0; i2 < 8; i2++) {
        int y = (i2<<5) + ly;
        sm[y*9 + lx] = g_T[IDX(fb + (y<<8) + x0 + lx)];
    }
    __syncthreads();
    int warp = threadIdx.x >> 5, lane = threadIdx.x & 31;
    fft256_sm(sm + warp, 9, lane, 1);
    __syncthreads();
    #pragma unroll
    for (int i2 = 0; i2 < 8; i2++) {
        int y = (i2<<5) + ly;
        int idx = IDX(fb + (y<<8) + x0 + lx);
        float2 v = sm[y*9 + lx];
        v = make_float2(v.x*0.0625f, v.y*0.0625f);
        g_x1[idx] = v; g_x2[idx] = v; g_u1[idx] = v; g_u2[idx] = v;
    }
}

// FUSED column pass: forward col FFT -> y1 dual update -> inverse col FFT.
// Input g_T holds row-FFT of (u1+u2). Output g_T holds col-inverse of updated y1.
__global__ __launch_bounds__(256) void k_col_fused() {
    __shared__ float2 sm[256*9];
    int f = blockIdx.x >> 5, x0 = (blockIdx.x & 31) << 3;
    int fb = f << 16;
    int lx = threadIdx.x & 7, ly = threadIdx.x >> 3;
    #pragma unroll
    for (int i2 = 0; i2 < 8; i2++) {
        int y = (i2<<5) + ly;
        sm[y*9 + lx] = g_T[IDX(fb + (y<<8) + x0 + lx)];
    }
    __syncthreads();
    int warp = threadIdx.x >> 5, lane = threadIdx.x & 31;
    fft256_sm(sm + warp, 9, lane, 0);     // forward column FFT
    __syncthreads();
    // y1' = (y1 + sigma*(Ku1 - D)) / (1+sigma); keep y1' in smem for inverse FFT
    #pragma unroll
    for (int i2 = 0; i2 < 8; i2++) {
        int y = (i2<<5) + ly;
        int idx = IDX(fb + (y<<8) + x0 + lx);
        float2 v = sm[y*9 + lx];
        v.x *= 0.0625f; v.y *= 0.0625f;   // true Ku1
        float2 d = g_D[idx];
        float2 yv = g_y1[idx];
        yv.x = (yv.x + SIGMA*(v.x - d.x)) * INV1PS;
        yv.y = (yv.y + SIGMA*(v.y - d.y)) * INV1PS;
        g_y1[idx] = yv;
        sm[y*9 + lx] = yv;
    }
    __syncthreads();
    fft256_sm(sm + warp, 9, lane, 1);     // inverse column FFT of y1'
    __syncthreads();
    #pragma unroll
    for (int i2 = 0; i2 < 8; i2++) {
        int y = (i2<<5) + ly;
        float2 v = sm[y*9 + lx];
        g_T[IDX(fb + (y<<8) + x0 + lx)] = make_float2(v.x*0.0625f, v.y*0.0625f);
    }
}

// inverse ROW pass of g_T -> Kadjy1; fused argg1 = x1 - tau*Kadjy1 and x2/u2 updates
__global__ __launch_bounds__(256) void k_row_kadj() {
    __shared__ float2 smr[8*256];
    int warp = threadIdx.x >> 5, lane = threadIdx.x & 31;
    int line = (blockIdx.x << 3) + warp;
    int base = line << 8;
    int f = line >> 8;
    float2* s = smr + (warp << 8);
    #pragma unroll
    for (int j = 0; j < 8; j++) { int i = lane + (j<<5); s[i] = g_T[IDX(base+i)]; }
    __syncwarp();
    fft256_sm(s, 1, lane, 1);
    #pragma unroll
    for (int j = 0; j < 8; j++) {
        int i = lane + (j<<5);
        int idx = IDX(base + i);
        float2 v = s[i];
        v.x *= 0.0625f; v.y *= 0.0625f;   // Kadjy1
        float2 x = g_x1[idx];
        g_A1[idx] = make_float2(x.x - TAU*v.x, x.y - TAU*v.y);
        float2 kadj;
        if (f == 0) {
            float2 yc = g_y2[idx];
            kadj = make_float2(v.x - yc.x, v.y - yc.y);
        } else if (f == NFR-1) {
            float2 ym = g_y2[IDX(idx - NPX)];
            kadj = make_float2(v.x + ym.x, v.y + ym.y);
        } else {
            float2 yc = g_y2[idx];
            float2 ym = g_y2[IDX(idx - NPX)];
            kadj = make_float2(v.x - (yc.x - ym.x), v.y - (yc.y - ym.y));
        }
        float2 xo = g_x2[idx];
        float2 xn = make_float2(xo.x - TAU*kadj.x, xo.y - TAU*kadj.y);
        g_x2[idx] = xn;
        g_u2[idx] = make_float2(2.f*xn.x - xo.x, 2.f*xn.y - xo.y);
    }
}

// Gram partials with 4x4 register blocking.
__global__ __launch_bounds__(256) void k_gram() {
    __shared__ float2 tile[64][33];
    int tid = threadIdx.x;
    int tx = tid & 15, ty = tid >> 4;
    float2 acc[4][4];
    #pragma unroll
    for (int i = 0; i < 4; i++)
        #pragma unroll
        for (int j = 0; j < 4; j++) acc[i][j] = make_float2(0.f, 0.f);
    int p0 = blockIdx.x * (NPX / GRAMB);   // 512 pixels per block
    for (int pt = 0; pt < NPX/GRAMB; pt += 32) {
        for (int l = tid; l < 2048; l += 256) {
            int gg = l >> 5, pp = l & 31;
            tile[gg][pp] = g_A1[IDX(gg*NPX + p0 + pt + pp)];
        }
        __syncthreads();
        for (int p = 0; p < 32; p++) {
            float2 ag[4], bh[4];
            #pragma unroll
            for (int i = 0; i < 4; i++) ag[i] = tile[ty + 16*i][p];
            #pragma unroll
            for (int j = 0; j < 4; j++) bh[j] = tile[tx + 16*j][p];
            #pragma unroll
            for (int i = 0; i < 4; i++)
                #pragma unroll
                for (int j = 0; j < 4; j++) {
                    float2 a = ag[i], b = bh[j];
                    acc[i][j].x += a.x*b.x + a.y*b.y;   // conj(a)*b
                    acc[i][j].y += a.x*b.y - a.y*b.x;
                }
        }
        __syncthreads();
    }
    #pragma unroll
    for (int i = 0; i < 4; i++)
        #pragma unroll
        for (int j = 0; j < 4; j++)
            g_Gp[blockIdx.x & (GRAMB-1)][((ty+16*i)*64 + tx+16*j) & 4095] = acc[i][j];
}

__global__ __launch_bounds__(256) void k_gramred() {
    int idx = (blockIdx.x*blockDim.x + threadIdx.x) & 4095;
    double sx = 0.0, sy = 0.0;
    for (int b = 0; b < GRAMB; b++) {
        float2 v = g_Gp[b][idx];
        sx += (double)v.x; sy += (double)v.y;
    }
    g_Gf[idx] = make_float2((float)sx, (float)sy);
}

// rotation computation for pair k of round rnd (reads A only)
__device__ __forceinline__ void rot_compute(const float2* A, const ushort2* pq,
                                            int rnd, int k, float* csr, float2* ssr) {
    ushort2 e = pq[rnd*32 + k];
    int p = e.x, q = e.y;
    float app = A[p*ELD+p].x, aqq = A[q*ELD+q].x;
    float2 apq = A[p*ELD+q];
    float ab = sqrtf(apq.x*apq.x + apq.y*apq.y);
    float c = 1.f; float2 s = make_float2(0.f, 0.f);
    if (ab > 1e-30f) {
        float tt = (aqq - app) / (2.f*ab);
        float t  = 1.f / (fabsf(tt) + sqrtf(1.f + tt*tt));
        if (tt < 0.f) t = -t;
        c = rsqrtf(1.f + t*t);
        float sg = t * c;
        s = make_float2(apq.x/ab*sg, apq.y/ab*sg);
    }
    csr[k] = c; ssr[k] = s;
}

// ---- 64x64 Hermitian eigensolver: software-pipelined parallel Jacobi ----
// 1024 threads. Per round: phase1 = A update (all warps);
// phase2 = warp0 computes next round's rotations WHILE warps 1-31 update V.
// Precomputed (p,q) tables; double-buffered rotations.
__global__ __launch_bounds__(1024) void k_eig(const float* __restrict__ lamLp, int lamIdx) {
    extern __shared__ float2 es[];
    float2*  A  = es;                        // 64*ELD = 4160 float2
    float2*  Vt = es + 64*ELD;               // 4096 float2: Vt[i*64+r] = V[r][i]
    ushort2* pq = (ushort2*)(es + 64*ELD + 4096);  // 63*32 entries
    __shared__ float  csr2[2][32];
    __shared__ float2 ssr2[2][32];
    __shared__ float  rr[64];
    int tid = threadIdx.x;   // 1024 threads

    for (int l = tid; l < 4096; l += 1024) {
        int r = l >> 6, c = l & 63;
        A[r*ELD + c] = g_Gf[l & 4095];
        Vt[l & 4095] = (r == c) ? make_float2(1.f, 0.f) : make_float2(0.f, 0.f);
    }
    for (int l = tid; l < 63*32; l += 1024) {
        int rnd = l >> 5, k = l & 31;
        int p, q;
        if (k == 0) { p = 63; q = rnd; }
        else { p = (rnd + k) % 63; q = (rnd - k + 63) % 63; }
        pq[l] = make_ushort2((unsigned short)p, (unsigned short)q);
    }
    __syncthreads();

    // prologue: rotations for round 0
    if (tid < 32) rot_compute(A, pq, 0, tid, csr2[0], ssr2[0]);
    __syncthreads();

    const int R = NSWEEP*63;
    int rnd = 0;
    for (int r = 0; r < R; r++) {
        int cur = r & 1, nxt = cur ^ 1;
        int nrnd = (rnd + 1 == 63) ? 0 : rnd + 1;
        // phase1: A update, one disjoint 2x2 block per thread
        {
            int kr = tid >> 5, kc = tid & 31;
            ushort2 er = pq[rnd*32 + kr], ec = pq[rnd*32 + kc];
            int p_r = er.x, q_r = er.y, p_c = ec.x, q_c = ec.y;
            float cc = csr2[cur][kc]; float2 sc = ssr2[cur][kc];
            float cr = csr2[cur][kr]; float2 sr = ssr2[cur][kr];
            float2 app = A[p_r*ELD+p_c], apq = A[p_r*ELD+q_c];
            float2 aqp = A[q_r*ELD+p_c], aqq = A[q_r*ELD+q_c];
            float2 bpp = csub(cscale(app, cc), cjmul(sc, apq));
            float2 bpq = cadd(cmulf(sc, app), cscale(apq, cc));
            float2 bqp = csub(cscale(aqp, cc), cjmul(sc, aqq));
            float2 bqq = cadd(cmulf(sc, aqp), cscale(aqq, cc));
            A[p_r*ELD+p_c] = csub(cscale(bpp, cr), cmulf(sr, bqp));
            A[p_r*ELD+q_c] = csub(cscale(bpq, cr), cmulf(sr, bqq));
            A[q_r*ELD+p_c] = cadd(cjmul(sr, bpp), cscale(bqp, cr));
            A[q_r*ELD+q_c] = cadd(cjmul(sr, bpq), cscale(bqq, cr));
        }
        __syncthreads();
        // phase2: warp0 -> rotations for r+1; warps 1..31 -> V update for r
        if (tid < 32) {
            if (r + 1 < R) rot_compute(A, pq, nrnd, tid, csr2[nxt], ssr2[nxt]);
        } else {
            int u = tid - 32;
            #pragma unroll
            for (int pass = 0; pass < 2; pass++) {
                int uu = (pass == 0) ? u : u + 992;
                if (pass == 1 && u >= 32) break;
                int k = uu >> 5, ch = uu & 31;
                ushort2 e = pq[rnd*32 + k];
                int p = e.x, q = e.y;
                float c = csr2[cur][k]; float2 s = ssr2[cur][k];
                int r2 = ch << 1;
                float4* vp4 = reinterpret_cast<float4*>(&Vt[p*64 + r2]);
                float4* vq4 = reinterpret_cast<float4*>(&Vt[q*64 + r2]);
                float4 vp = *vp4, vq = *vq4;
                float2 vp0 = make_float2(vp.x, vp.y), vp1 = make_float2(vp.z, vp.w);
                float2 vq0 = make_float2(vq.x, vq.y), vq1 = make_float2(vq.z, vq.w);
                float2 np0 = csub(cscale(vp0, c), cjmul(s, vq0));
                float2 nq0 = cadd(cmulf(s, vp0), cscale(vq0, c));
                float2 np1 = csub(cscale(vp1, c), cjmul(s, vq1));
                float2 nq1 = cadd(cmulf(s, vp1), cscale(vq1, c));
                *vp4 = make_float4(np0.x, np0.y, np1.x, np1.y);
                *vq4 = make_float4(nq0.x, nq0.y, nq1.x, nq1.y);
            }
        }
        __syncthreads();
        rnd = nrnd;
    }

    if (tid == 0) {
        float lmax = 0.f;
        for (int i = 0; i < 64; i++) { float l = A[i*ELD+i].x; if (l > lmax) lmax = l; }
        float lamL = lamLp ? fmaxf(lamLp[lamIdx], 0.f) : 0.8f;
        float thr = sqrtf(fmaxf(lmax, 0.f)) * TAU * lamL;
        for (int i = 0; i < 64; i++) {
            float l  = fmaxf(A[i*ELD+i].x, 0.f);
            float sv = sqrtf(l);
            rr[i] = (sv > thr) ? (sv - thr) / sv : 0.f;
        }
    }
    __syncthreads();
    // W[g][f] = sum_i Vt[i][g] * r_i * conj(Vt[i][f])
    {
        int g = tid & 63, f0 = (tid >> 6) << 2;
        float2 w[4];
        #pragma unroll
        for (int j = 0; j < 4; j++) w[j] = make_float2(0.f, 0.f);
        for (int i = 0; i < 64; i++) {
            float2 vg = Vt[i*64 + g];
            float r_ = rr[i];
            float ax = vg.x*r_, ay = vg.y*r_;
            #pragma unroll
            for (int j = 0; j < 4; j++) {
                float2 vf = Vt[i*64 + f0 + j];
                w[j].x += ax*vf.x + ay*vf.y;
                w[j].y += ay*vf.x - ax*vf.y;
            }
        }
        #pragma unroll
        for (int j = 0; j < 4; j++)
            g_W[(g*64 + f0 + j) & 4095] = w[j];
    }
}

// x1new[f][p] = sum_g A1[g][p] * W[g][f]; u1 = 2*x1new - x1old
__global__ __launch_bounds__(256) void k_gemm() {
    __shared__ float2 Ws[64*64];
    __shared__ float2 Asm[8][64];
    int tid = threadIdx.x;
    for (int l = tid; l < 4096; l += 256) Ws[l] = g_W[l & 4095];
    int px0 = (tid & 15) << 2;
    int f0  = (tid >> 4) << 2;
    int p0 = blockIdx.x << 6;
    float2 acc[4][4];
    #pragma unroll
    for (int i = 0; i < 4; i++)
        #pragma unroll
        for (int j = 0; j < 4; j++) acc[i][j] = make_float2(0.f, 0.f);
    __syncthreads();
    for (int g0 = 0; g0 < 64; g0 += 8) {
        for (int l = tid; l < 512; l += 256) {
            int gg = l >> 6, pp = l & 63;
            Asm[gg][pp] = g_A1[IDX((g0+gg)*NPX + p0 + pp)];
        }
        __syncthreads();
        #pragma unroll
        for (int gg = 0; gg < 8; gg++) {
            float4 a01 = *reinterpret_cast<const float4*>(&Asm[gg][px0]);
            float4 a23 = *reinterpret_cast<const float4*>(&Asm[gg][px0+2]);
            float4 w01 = *reinterpret_cast<const float4*>(&Ws[(g0+gg)*64 + f0]);
            float4 w23 = *reinterpret_cast<const float4*>(&Ws[(g0+gg)*64 + f0 + 2]);
            float2 a[4] = { make_float2(a01.x,a01.y), make_float2(a01.z,a01.w),
                            make_float2(a23.x,a23.y), make_float2(a23.z,a23.w) };
            float2 w[4] = { make_float2(w01.x,w01.y), make_float2(w01.z,w01.w),
                            make_float2(w23.x,w23.y), make_float2(w23.z,w23.w) };
            #pragma unroll
            for (int i = 0; i < 4; i++)
                #pragma unroll
                for (int j = 0; j < 4; j++) {
                    acc[i][j].x += a[i].x*w[j].x - a[i].y*w[j].y;
                    acc[i][j].y += a[i].x*w[j].y + a[i].y*w[j].x;
                }
        }
        __syncthreads();
    }
    #pragma unroll
    for (int j = 0; j < 4; j++) {
        #pragma unroll
        for (int i = 0; i < 4; i++) {
            int idx = IDX((f0+j)*NPX + p0 + px0 + i);
            float2 old = g_x1[idx];
            float2 nv  = acc[i][j];
            g_x1[idx] = nv;
            g_u1[idx] = make_float2(2.f*nv.x - old.x, 2.f*nv.y - old.y);
        }
    }
}

// Output writer: buffer is out_size float32 elements; write re(x1+x2).
__global__ __launch_bounds__(256) void k_out(float* __restrict__ out, int nf) {
    for (int i = blockIdx.x*blockDim.x + threadIdx.x; i < nf; i += gridDim.x*blockDim.x) {
        int ii = IDX(i);
        out[i] = g_x1[ii].x + g_x2[ii].x;
    }
}

// ---------------- launch ----------------
extern "C" void kernel_launch(void* const* d_in, const int* in_sizes, int n_in,
                              void* d_out, int out_size) {
    const float* dr = 0; const float* di = 0;
    const float* lamS = 0; const float* lamL = 0;
    int drCap = 0, diCap = 0, lamScnt = 0, lamLcnt = 0;
    for (int i = 0; i < n_in; i++) {
        int sz = in_sizes[i];
        if (sz >= NTOT) {
            if (!dr)      { dr = (const float*)d_in[i]; drCap = sz; }
            else if (!di) { di = (const float*)d_in[i]; diCap = sz; }
        } else if (sz > 0) {
            if (!lamS)      { lamS = (const float*)d_in[i]; lamScnt = sz; }
            else if (!lamL) { lamL = (const float*)d_in[i]; lamLcnt = sz; }
        }
    }
    if (!dr && n_in > 0) { dr = (const float*)d_in[0]; drCap = in_sizes[0]; }
    if (!di && n_in > 1) { di = (const float*)d_in[1]; diCap = in_sizes[1]; }
    int cap = drCap < diCap ? drCap : diCap;
    if (cap > NTOT) cap = NTOT;
    if (cap < 0) cap = 0;

    int nf = out_size;
    if (nf > NTOT) nf = NTOT;
    if (nf < 0) nf = 0;

    // dynamic smem: A (64*ELD) + Vt (4096) float2 + pq (63*32 ushort2)
    const int eig_smem = (int)((64*ELD + 4096) * sizeof(float2) + 63*32*sizeof(ushort2));
    cudaFuncSetAttribute(k_eig, cudaFuncAttributeMaxDynamicSharedMemorySize, eig_smem);

    k_init<<<1, 128>>>();
    k_sumsq<<<256, 256>>>(dr, di, cap);
    k_normred<<<1, 256>>>();
    k_buildD<<<4096, 256>>>(dr, di, cap);

    // startpoint = ifft2(D) -> x1, x2, u1, u2
    k_fft_row<<<2048, 256>>>(0, 1, (const float*)0, 0);
    k_col_start<<<2048, 256>>>();

    for (int it = 0; it < 8; it++) {
        int sIdx = (lamScnt > it) ? it : (lamScnt > 0 ? lamScnt - 1 : 0);
        int lIdx = (lamLcnt > it) ? it : (lamLcnt > 0 ? lamLcnt - 1 : 0);
        // rows fwd (+ y2 update) -> fused cols (fwd + y1 + inv) -> rows inv (+ kadj)
        k_fft_row<<<2048, 256>>>(1, 0, lamS, sIdx);
        k_col_fused<<<2048, 256>>>();
        k_row_kadj<<<2048, 256>>>();
        // low-rank prox
        k_gram<<<GRAMB, 256>>>();
        k_gramred<<<16, 256>>>();
        k_eig<<<1, 1024, eig_smem>>>(lamL, lIdx);
        k_gemm<<<1024, 256>>>();
    }

    k_out<<<4096, 256>>>((float*)d_out, nf);
}